// round 2
// baseline (speedup 1.0000x reference)
#include <cuda_runtime.h>
#include <cuda_bf16.h>
#include <cstdint>

// Problem constants
#define B_   8
#define K_   1024
#define N_   (B_ * K_)      // 8192 conditioning steps
#define S_   64             // samples per step (T/K)
#define T_   65536
#define CIN  64
#define COUT 64
#define CKS  128            // CH_IN * KSIZE
#define HID_ 32
#define ZDIM 128
#define RTOT (CKS * COUT)   // 8192 rows of w2

// Device scratch (allowed: __device__ globals, no runtime alloc)
__device__ float g_h1[N_ * HID_];          // 1 MB
__device__ float g_bias[N_ * COUT];        // 2 MB
__device__ float g_weight[(size_t)N_ * RTOT]; // 256 MiB: [n][c*64+o]

// ---------------------------------------------------------------------------
// Kernel 1: hyper MLP heads. grid = (16 ktiles, 8 b), block = 256.
// Computes g_h1[n][32] = relu(w1 @ z + b1) and g_bias[n][64] = w4 @ relu(w3 z + b3) + b4
// ---------------------------------------------------------------------------
__global__ __launch_bounds__(256) void hyper_kernel(
    const float* __restrict__ z,
    const float* __restrict__ w1, const float* __restrict__ b1,
    const float* __restrict__ w3, const float* __restrict__ b3,
    const float* __restrict__ w4, const float* __restrict__ b4)
{
    __shared__ float zs[ZDIM * 64];   // [j][kk]  32 KB
    __shared__ float h3s[HID_ * 64];  // [jo][kk]  8 KB

    const int b  = blockIdx.y;
    const int k0 = blockIdx.x * 64;
    const int tid = threadIdx.x;

    // load z tile: z[b, j, k0+kk], contiguous in kk
    #pragma unroll
    for (int i = 0; i < 32; ++i) {
        int f = i * 256 + tid;           // 8192 elems
        int j = f >> 6, kk = f & 63;
        zs[f] = z[((size_t)(b * ZDIM + j)) * K_ + k0 + kk];
    }
    __syncthreads();

    // h1: 32 out x 64 kk
    #pragma unroll
    for (int i = 0; i < 8; ++i) {
        int idx = i * 256 + tid;         // 2048
        int jo = idx >> 6, kk = idx & 63;
        float acc = b1[jo];
        #pragma unroll 8
        for (int j = 0; j < ZDIM; ++j)
            acc += w1[jo * ZDIM + j] * zs[j * 64 + kk];
        g_h1[(size_t)(b * K_ + k0 + kk) * HID_ + jo] = fmaxf(acc, 0.f);
    }

    // h3 -> smem
    #pragma unroll
    for (int i = 0; i < 8; ++i) {
        int idx = i * 256 + tid;
        int jo = idx >> 6, kk = idx & 63;
        float acc = b3[jo];
        #pragma unroll 8
        for (int j = 0; j < ZDIM; ++j)
            acc += w3[jo * ZDIM + j] * zs[j * 64 + kk];
        h3s[jo * 64 + kk] = fmaxf(acc, 0.f);
    }
    __syncthreads();

    // bias: 64 o x 64 kk
    #pragma unroll
    for (int i = 0; i < 16; ++i) {
        int idx = i * 256 + tid;         // 4096
        int o = idx >> 6, kk = idx & 63;
        float acc = b4[o];
        #pragma unroll
        for (int j = 0; j < HID_; ++j)
            acc += w4[o * HID_ + j] * h3s[j * 64 + kk];
        g_bias[(size_t)(b * K_ + k0 + kk) * COUT + o] = acc;
    }
}

// ---------------------------------------------------------------------------
// Kernel 2: weight generation GEMM. out[n][r] = w2[r,:].h1[n,:] + b2[r]
// grid = (64 rtiles, 128 ntiles), block = 128. Tile: 64 n x 128 r.
// Thread tile: 8 n x 8 r (64 accumulators). FMA-bound.
// ---------------------------------------------------------------------------
__global__ __launch_bounds__(128) void wgen_kernel(
    const float* __restrict__ w2, const float* __restrict__ b2)
{
    __shared__ float h1sT[HID_ * 64];   // [j][n]   8 KB
    __shared__ float w2sT[HID_ * 128];  // [j][r]  16 KB

    const int rtile = blockIdx.x;       // 0..63
    const int ntile = blockIdx.y;       // 0..127
    const int tid = threadIdx.x;

    const float* hsrc = g_h1 + (size_t)ntile * 64 * HID_;
    #pragma unroll
    for (int i = 0; i < 16; ++i) {
        int f = i * 128 + tid;           // 2048
        int n = f >> 5, j = f & 31;
        h1sT[j * 64 + n] = hsrc[f];
    }
    const float* wsrc = w2 + (size_t)rtile * 128 * HID_;
    #pragma unroll
    for (int i = 0; i < 32; ++i) {
        int f = i * 128 + tid;           // 4096
        int r = f >> 5, j = f & 31;
        w2sT[j * 128 + r] = wsrc[f];
    }
    __syncthreads();

    const int ng = tid & 7;              // 8 groups of n
    const int rg = tid >> 3;             // 16 groups of r
    const int n0 = ng * 8;
    const int r0 = rg * 8;

    float acc[8][8];
    #pragma unroll
    for (int a = 0; a < 8; ++a)
        #pragma unroll
        for (int c = 0; c < 8; ++c) acc[a][c] = 0.f;

    #pragma unroll 4
    for (int j = 0; j < HID_; ++j) {
        float4 h0 = *(const float4*)(h1sT + j * 64 + n0);
        float4 h1v = *(const float4*)(h1sT + j * 64 + n0 + 4);
        float4 v0 = *(const float4*)(w2sT + j * 128 + r0);
        float4 v1 = *(const float4*)(w2sT + j * 128 + r0 + 4);
        const float hh[8] = {h0.x, h0.y, h0.z, h0.w, h1v.x, h1v.y, h1v.z, h1v.w};
        const float ww[8] = {v0.x, v0.y, v0.z, v0.w, v1.x, v1.y, v1.z, v1.w};
        #pragma unroll
        for (int a = 0; a < 8; ++a)
            #pragma unroll
            for (int c = 0; c < 8; ++c)
                acc[a][c] += hh[a] * ww[c];
    }

    const int rbase = rtile * 128 + r0;
    float bb[8];
    #pragma unroll
    for (int c = 0; c < 8; ++c) bb[c] = b2[rbase + c];

    #pragma unroll
    for (int a = 0; a < 8; ++a) {
        size_t row = (size_t)(ntile * 64 + n0 + a);
        float* dst = g_weight + row * RTOT + rbase;
        float4 s0 = {acc[a][0] + bb[0], acc[a][1] + bb[1], acc[a][2] + bb[2], acc[a][3] + bb[3]};
        float4 s1 = {acc[a][4] + bb[4], acc[a][5] + bb[5], acc[a][6] + bb[6], acc[a][7] + bb[7]};
        *(float4*)(dst)     = s0;
        *(float4*)(dst + 4) = s1;
    }
}

// ---------------------------------------------------------------------------
// Kernel 3: main batched GEMM. One CTA per n=(b,k). block = 256.
// y[s,o] = sum_c xr[s,c] * W[c,o] + bias[o]
// smem: Xrs[128][64] (c-major, s contiguous), Ws[128][64] (c-major, o contiguous)
// Thread tile: 4 o x 4 s; stores are float4 over s (32B-sector perfect).
// ---------------------------------------------------------------------------
__global__ __launch_bounds__(256) void main_kernel(
    const float* __restrict__ x, float* __restrict__ out)
{
    extern __shared__ float sm[];
    float* Xrs = sm;           // 8192 floats
    float* Ws  = sm + 8192;    // 8192 floats

    const int n = blockIdx.x;
    const int b = n >> 10;
    const int k = n & 1023;
    const int tid = threadIdx.x;

    const float* xb = x + (size_t)b * CIN * T_ + k * 64;

    // load unshifted x tile: 64 ch x 64 t (c < 64 half of Xrs)
    #pragma unroll
    for (int i = 0; i < 4; ++i) {
        int f = i * 256 + tid;            // float4 index, 1024 total
        int ch = f >> 4;
        int sc = (f & 15) * 4;
        float4 v = *(const float4*)(xb + (size_t)ch * T_ + sc);
        *(float4*)(Xrs + ch * 64 + sc) = v;
    }
    // load generated weight tile [128][64]
    const float4* wg = (const float4*)(g_weight + (size_t)n * RTOT);
    float4* wsv = (float4*)Ws;
    #pragma unroll
    for (int i = 0; i < 8; ++i)
        wsv[i * 256 + tid] = wg[i * 256 + tid];
    __syncthreads();

    // build shifted half: Xrs[64+ch][s] = (s>0) ? Xrs[ch][s-1] : (k>0 ? x[b,ch,k*64-1] : 0)
    #pragma unroll
    for (int i = 0; i < 16; ++i) {
        int e = i * 256 + tid;            // 4096
        int ch = e >> 6, s = e & 63;
        float v;
        if (s) v = Xrs[ch * 64 + s - 1];
        else   v = k ? xb[(size_t)ch * T_ - 1] : 0.f;
        Xrs[(64 + ch) * 64 + s] = v;
    }
    __syncthreads();

    const int og = tid & 15;   // 16 o-groups
    const int sg = tid >> 4;   // 16 s-groups
    const int o0 = og * 4;
    const int s0 = sg * 4;

    float acc[4][4];
    #pragma unroll
    for (int a = 0; a < 4; ++a)
        #pragma unroll
        for (int c = 0; c < 4; ++c) acc[a][c] = 0.f;

    #pragma unroll 8
    for (int c = 0; c < CKS; ++c) {
        float4 xv = *(const float4*)(Xrs + (c << 6) + s0);
        float4 wv = *(const float4*)(Ws  + (c << 6) + o0);
        const float xs[4] = {xv.x, xv.y, xv.z, xv.w};
        const float wo[4] = {wv.x, wv.y, wv.z, wv.w};
        #pragma unroll
        for (int oi = 0; oi < 4; ++oi)
            #pragma unroll
            for (int si = 0; si < 4; ++si)
                acc[oi][si] += wo[oi] * xs[si];
    }

    const float* bn = g_bias + (size_t)n * COUT;
    float* ob = out + (size_t)b * COUT * T_ + k * 64;
    #pragma unroll
    for (int oi = 0; oi < 4; ++oi) {
        float bv = bn[o0 + oi];
        float4 v = {acc[oi][0] + bv, acc[oi][1] + bv, acc[oi][2] + bv, acc[oi][3] + bv};
        *(float4*)(ob + (size_t)(o0 + oi) * T_ + s0) = v;
    }
}

// ---------------------------------------------------------------------------
extern "C" void kernel_launch(void* const* d_in, const int* in_sizes, int n_in,
                              void* d_out, int out_size)
{
    const float* x  = (const float*)d_in[0];
    const float* z  = (const float*)d_in[1];
    const float* w1 = (const float*)d_in[2];
    const float* b1 = (const float*)d_in[3];
    const float* w2 = (const float*)d_in[4];
    const float* b2 = (const float*)d_in[5];
    const float* w3 = (const float*)d_in[6];
    const float* b3 = (const float*)d_in[7];
    const float* w4 = (const float*)d_in[8];
    const float* b4 = (const float*)d_in[9];
    float* out = (float*)d_out;

    hyper_kernel<<<dim3(16, 8), 256>>>(z, w1, b1, w3, b3, w4, b4);
    wgen_kernel<<<dim3(64, 128), 128>>>(w2, b2);

    cudaFuncSetAttribute(main_kernel, cudaFuncAttributeMaxDynamicSharedMemorySize, 65536);
    main_kernel<<<N_, 256, 65536>>>(x, out);
}

// round 3
// speedup vs baseline: 1.0271x; 1.0271x over previous
#include <cuda_runtime.h>
#include <cuda_bf16.h>
#include <cstdint>

typedef unsigned long long ull;

// Problem constants
#define B_   8
#define K_   1024
#define N_   (B_ * K_)      // 8192 conditioning steps
#define S_   64             // samples per step (T/K)
#define T_   65536
#define CIN  64
#define COUT 64
#define CKS  128            // CH_IN * KSIZE
#define HID_ 32
#define ZDIM 128
#define RTOT (CKS * COUT)   // 8192 rows of w2

// Device scratch
__device__ float g_h1[N_ * HID_];              // 1 MB   [n][j]
__device__ float g_bias[N_ * COUT];            // 2 MB   [n][o]
__device__ float g_weight[(size_t)N_ * RTOT];  // 256 MiB [n][c*64+o]

// ---------------------------------------------------------------------------
// Packed fp32x2 helpers (Blackwell FFMA2 path — PTX only)
// ---------------------------------------------------------------------------
__device__ __forceinline__ void fma2(ull& d, ull a, ull b) {
    asm("fma.rn.f32x2 %0, %1, %2, %0;" : "+l"(d) : "l"(a), "l"(b));
}
__device__ __forceinline__ ull dup2(float v) {
    ull r; unsigned u = __float_as_uint(v);
    asm("mov.b64 %0, {%1, %2};" : "=l"(r) : "r"(u), "r"(u));
    return r;
}
__device__ __forceinline__ float lo32(ull v) { return __uint_as_float((unsigned)v); }
__device__ __forceinline__ float hi32(ull v) { return __uint_as_float((unsigned)(v >> 32)); }

// ---------------------------------------------------------------------------
// Kernel 1: hyper MLP heads. grid = (32 ktiles, 8 b), block = 256, dyn smem.
// All operand matrices staged in smem (conflict-free padded transposes).
// ---------------------------------------------------------------------------
__global__ __launch_bounds__(256) void hyper_kernel(
    const float* __restrict__ z,
    const float* __restrict__ w1, const float* __restrict__ b1,
    const float* __restrict__ w3, const float* __restrict__ b3,
    const float* __restrict__ w4, const float* __restrict__ b4)
{
    extern __shared__ float hs[];
    float* zs   = hs;            // 128*32 = 4096
    float* w1sT = hs + 4096;     // 128*33 = 4224  [j][jo] padded
    float* w3sT = hs + 8320;     // 4224
    float* w4sT = hs + 12544;    // 32*65 = 2080   [j][o] padded
    float* h3s  = hs + 14624;    // 32*32 = 1024   [kk][j]

    const int b  = blockIdx.y;
    const int k0 = blockIdx.x * 32;
    const int tid = threadIdx.x;

    // z tile: [j][kk], kk contiguous
    #pragma unroll
    for (int i = 0; i < 16; ++i) {
        int f = i * 256 + tid;               // 4096
        zs[f] = z[((size_t)(b * ZDIM + (f >> 5))) * K_ + k0 + (f & 31)];
    }
    // w1, w3 transposed with pad 33 (conflict-free write: stride 33)
    #pragma unroll
    for (int i = 0; i < 16; ++i) {
        int f = i * 256 + tid;               // 4096
        w1sT[(f & 127) * 33 + (f >> 7)] = w1[f];
    }
    #pragma unroll
    for (int i = 0; i < 16; ++i) {
        int f = i * 256 + tid;
        w3sT[(f & 127) * 33 + (f >> 7)] = w3[f];
    }
    // w4 transposed with pad 65
    #pragma unroll
    for (int i = 0; i < 8; ++i) {
        int f = i * 256 + tid;               // 2048
        w4sT[(f & 31) * 65 + (f >> 5)] = w4[f];
    }
    __syncthreads();

    // h1: 32 jo x 32 kk  (lanes = jo -> coalesced g_h1 store)
    #pragma unroll
    for (int i = 0; i < 4; ++i) {
        int idx = i * 256 + tid;             // 1024
        int jo = idx & 31, kk = idx >> 5;
        float acc = b1[jo];
        #pragma unroll 8
        for (int j = 0; j < ZDIM; ++j)
            acc += w1sT[j * 33 + jo] * zs[j * 32 + kk];
        g_h1[(size_t)(b * K_ + k0 + kk) * HID_ + jo] = fmaxf(acc, 0.f);
    }
    // h3 -> smem [kk][j]
    #pragma unroll
    for (int i = 0; i < 4; ++i) {
        int idx = i * 256 + tid;
        int jo = idx & 31, kk = idx >> 5;
        float acc = b3[jo];
        #pragma unroll 8
        for (int j = 0; j < ZDIM; ++j)
            acc += w3sT[j * 33 + jo] * zs[j * 32 + kk];
        h3s[kk * 32 + jo] = fmaxf(acc, 0.f);
    }
    __syncthreads();

    // bias: 64 o x 32 kk  (lanes = o -> coalesced g_bias store)
    #pragma unroll
    for (int i = 0; i < 8; ++i) {
        int idx = i * 256 + tid;             // 2048
        int o = idx & 63, kk = idx >> 6;
        float acc = b4[o];
        #pragma unroll
        for (int j = 0; j < HID_; ++j)
            acc += w4sT[j * 65 + o] * h3s[kk * 32 + j];
        g_bias[(size_t)(b * K_ + k0 + kk) * COUT + o] = acc;
    }
}

// ---------------------------------------------------------------------------
// Kernel 2: weight generation GEMM via f32x2.
// out[n][r] = w2[r,:].h1[n,:] + b2[r]; grid (64 rtiles, 128 ntiles), block 128.
// Tile 64n x 128r; thread tile 8n x 8r (r packed in pairs).
// ---------------------------------------------------------------------------
__global__ __launch_bounds__(128) void wgen_kernel(
    const float* __restrict__ w2, const float* __restrict__ b2)
{
    __shared__ float h1sT[HID_ * 68];    // [j][n] pad 68 (16B-aligned rows)
    __shared__ float w2sT[HID_ * 132];   // [j][r] pad 132

    const int rtile = blockIdx.x;        // 0..63
    const int ntile = blockIdx.y;        // 0..127
    const int tid = threadIdx.x;

    const float* hsrc = g_h1 + (size_t)ntile * 64 * HID_;
    #pragma unroll
    for (int i = 0; i < 16; ++i) {
        int f = i * 128 + tid;           // 2048
        h1sT[(f & 31) * 68 + (f >> 5)] = hsrc[f];
    }
    const float* wsrc = w2 + (size_t)rtile * 128 * HID_;
    #pragma unroll
    for (int i = 0; i < 32; ++i) {
        int f = i * 128 + tid;           // 4096
        w2sT[(f & 31) * 132 + (f >> 5)] = wsrc[f];
    }
    __syncthreads();

    const int ng = tid & 7;              // 8 n-groups
    const int rg = tid >> 3;             // 16 r-groups
    const int n0 = ng * 8;
    const int r0 = rg * 8;

    ull acc[8][4];
    #pragma unroll
    for (int a = 0; a < 8; ++a)
        #pragma unroll
        for (int p = 0; p < 4; ++p) acc[a][p] = 0ull;

    #pragma unroll 8
    for (int j = 0; j < HID_; ++j) {
        float4 h0 = *(const float4*)(h1sT + j * 68 + n0);
        float4 h1v = *(const float4*)(h1sT + j * 68 + n0 + 4);
        ull hd[8] = {dup2(h0.x), dup2(h0.y), dup2(h0.z), dup2(h0.w),
                     dup2(h1v.x), dup2(h1v.y), dup2(h1v.z), dup2(h1v.w)};
        ulonglong2 wv0 = *(const ulonglong2*)(w2sT + j * 132 + r0);
        ulonglong2 wv1 = *(const ulonglong2*)(w2sT + j * 132 + r0 + 4);
        ull wp[4] = {wv0.x, wv0.y, wv1.x, wv1.y};
        #pragma unroll
        for (int a = 0; a < 8; ++a)
            #pragma unroll
            for (int p = 0; p < 4; ++p)
                fma2(acc[a][p], hd[a], wp[p]);
    }

    const int rbase = rtile * 128 + r0;
    float bb[8];
    #pragma unroll
    for (int c = 0; c < 8; ++c) bb[c] = b2[rbase + c];

    #pragma unroll
    for (int a = 0; a < 8; ++a) {
        size_t row = (size_t)(ntile * 64 + n0 + a);
        float* dst = g_weight + row * RTOT + rbase;
        float4 s0 = {lo32(acc[a][0]) + bb[0], hi32(acc[a][0]) + bb[1],
                     lo32(acc[a][1]) + bb[2], hi32(acc[a][1]) + bb[3]};
        float4 s1 = {lo32(acc[a][2]) + bb[4], hi32(acc[a][2]) + bb[5],
                     lo32(acc[a][3]) + bb[6], hi32(acc[a][3]) + bb[7]};
        *(float4*)(dst)     = s0;
        *(float4*)(dst + 4) = s1;
    }
}

// ---------------------------------------------------------------------------
// Kernel 3: main batched GEMM via f32x2. One CTA per n, block = 64.
// y[s,o] = sum_c xr[s,c] * W[c,o] + bias[o]
// Thread tile 8s x 8o; s packed in pairs. smem 64KB dyn -> 3 CTAs/SM.
// ---------------------------------------------------------------------------
__global__ __launch_bounds__(64, 3) void main_kernel(
    const float* __restrict__ x, float* __restrict__ out)
{
    extern __shared__ float sm[];
    float* Xrs = sm;           // 128 x 64 (c-major, s contiguous)
    float* Ws  = sm + 8192;    // 128 x 64 (c-major, o contiguous)

    const int n = blockIdx.x;
    const int b = n >> 10;
    const int k = n & 1023;
    const int tid = threadIdx.x;   // 0..63

    const float* xb = x + (size_t)b * CIN * T_ + k * 64;

    // load unshifted x (64ch x 64s) as float4: 1024 vec, 16/thread
    #pragma unroll
    for (int i = 0; i < 16; ++i) {
        int f = i * 64 + tid;
        int ch = f >> 4, sc = (f & 15) * 4;
        *(float4*)(Xrs + ch * 64 + sc) = *(const float4*)(xb + (size_t)ch * T_ + sc);
    }
    // load generated weight tile [128][64]: 2048 vec, 32/thread
    const float4* wg = (const float4*)(g_weight + (size_t)n * RTOT);
    float4* wsv = (float4*)Ws;
    #pragma unroll
    for (int i = 0; i < 32; ++i)
        wsv[i * 64 + tid] = wg[i * 64 + tid];
    __syncthreads();

    // shifted half: Xrs[64+ch][s] = (s>0) ? Xrs[ch][s-1] : (k>0 ? x[...,-1] : 0)
    #pragma unroll
    for (int i = 0; i < 64; ++i) {
        int e = i * 64 + tid;            // 4096
        int ch = e >> 6, s = e & 63;
        float v = s ? Xrs[ch * 64 + s - 1]
                    : (k ? xb[(size_t)ch * T_ - 1] : 0.f);
        Xrs[(64 + ch) * 64 + s] = v;
    }
    __syncthreads();

    const int og = tid & 7;    // 8 o-groups
    const int sg = tid >> 3;   // 8 s-groups
    const int o0 = og * 8;
    const int s0 = sg * 8;

    ull acc[8][4];
    #pragma unroll
    for (int a = 0; a < 8; ++a)
        #pragma unroll
        for (int p = 0; p < 4; ++p) acc[a][p] = 0ull;

    #pragma unroll 8
    for (int c = 0; c < CKS; ++c) {
        ulonglong2 xv0 = *(const ulonglong2*)(Xrs + (c << 6) + s0);
        ulonglong2 xv1 = *(const ulonglong2*)(Xrs + (c << 6) + s0 + 4);
        ull xs[4] = {xv0.x, xv0.y, xv1.x, xv1.y};
        float4 w0 = *(const float4*)(Ws + (c << 6) + o0);
        float4 w1 = *(const float4*)(Ws + (c << 6) + o0 + 4);
        ull wd[8] = {dup2(w0.x), dup2(w0.y), dup2(w0.z), dup2(w0.w),
                     dup2(w1.x), dup2(w1.y), dup2(w1.z), dup2(w1.w)};
        #pragma unroll
        for (int oi = 0; oi < 8; ++oi)
            #pragma unroll
            for (int p = 0; p < 4; ++p)
                fma2(acc[oi][p], wd[oi], xs[p]);
    }

    const float* bn = g_bias + (size_t)n * COUT;
    float* ob = out + (size_t)b * COUT * T_ + k * 64;
    #pragma unroll
    for (int oi = 0; oi < 8; ++oi) {
        float bv = bn[o0 + oi];
        float4 v0 = {lo32(acc[oi][0]) + bv, hi32(acc[oi][0]) + bv,
                     lo32(acc[oi][1]) + bv, hi32(acc[oi][1]) + bv};
        float4 v1 = {lo32(acc[oi][2]) + bv, hi32(acc[oi][2]) + bv,
                     lo32(acc[oi][3]) + bv, hi32(acc[oi][3]) + bv};
        float* dst = ob + (size_t)(o0 + oi) * T_ + s0;
        *(float4*)(dst)     = v0;
        *(float4*)(dst + 4) = v1;
    }
}

// ---------------------------------------------------------------------------
extern "C" void kernel_launch(void* const* d_in, const int* in_sizes, int n_in,
                              void* d_out, int out_size)
{
    const float* x  = (const float*)d_in[0];
    const float* z  = (const float*)d_in[1];
    const float* w1 = (const float*)d_in[2];
    const float* b1 = (const float*)d_in[3];
    const float* w2 = (const float*)d_in[4];
    const float* b2 = (const float*)d_in[5];
    const float* w3 = (const float*)d_in[6];
    const float* b3 = (const float*)d_in[7];
    const float* w4 = (const float*)d_in[8];
    const float* b4 = (const float*)d_in[9];
    float* out = (float*)d_out;

    static int attr_done = 0;
    if (!attr_done) {
        cudaFuncSetAttribute(hyper_kernel, cudaFuncAttributeMaxDynamicSharedMemorySize, 62592);
        cudaFuncSetAttribute(main_kernel,  cudaFuncAttributeMaxDynamicSharedMemorySize, 65536);
        attr_done = 1;
    }

    hyper_kernel<<<dim3(32, 8), 256, 62592>>>(z, w1, b1, w3, b3, w4, b4);
    wgen_kernel<<<dim3(64, 128), 128>>>(w2, b2);
    main_kernel<<<N_, 64, 65536>>>(x, out);
}

// round 6
// speedup vs baseline: 1.3420x; 1.3066x over previous
#include <cuda_runtime.h>
#include <cuda_bf16.h>
#include <cstdint>

// Problem constants
#define B_   8
#define K_   1024
#define N_   (B_ * K_)
#define S_   64
#define T_   65536
#define CIN  64
#define COUT 64
#define CKS  128
#define HID_ 32
#define ZDIM 128
#define RTOT (CKS * COUT)

// Device scratch
__device__ float g_h1[N_ * HID_];
__device__ float g_bias[N_ * COUT];
__device__ float g_weight[(size_t)N_ * RTOT];   // [n][r], r = c*64+o

// ---------------------------------------------------------------------------
// PTX helpers (base sm_80+ features only — no tcgen05)
// ---------------------------------------------------------------------------
__device__ __forceinline__ uint32_t smem_u32(const void* p) {
    uint32_t a;
    asm("{ .reg .u64 t; cvta.to.shared.u64 t, %1; cvt.u32.u64 %0, t; }" : "=r"(a) : "l"(p));
    return a;
}
#define LDSM_X4(r0,r1,r2,r3,addr) \
    asm volatile("ldmatrix.sync.aligned.m8n8.x4.shared.b16 {%0,%1,%2,%3}, [%4];" \
        : "=r"(r0),"=r"(r1),"=r"(r2),"=r"(r3) : "r"(addr))
#define LDSM_X2T(r0,r1,addr) \
    asm volatile("ldmatrix.sync.aligned.m8n8.x2.trans.shared.b16 {%0,%1}, [%2];" \
        : "=r"(r0),"=r"(r1) : "r"(addr))
#define MMA16816(d,a0,a1,a2,a3,b0,b1) \
    asm volatile("mma.sync.aligned.m16n8k16.row.col.f32.bf16.bf16.f32 " \
        "{%0,%1,%2,%3}, {%4,%5,%6,%7}, {%8,%9}, {%0,%1,%2,%3};" \
        : "+f"((d)[0]),"+f"((d)[1]),"+f"((d)[2]),"+f"((d)[3]) \
        : "r"(a0),"r"(a1),"r"(a2),"r"(a3),"r"(b0),"r"(b1))

__device__ __forceinline__ void sts16(uint32_t addr, __nv_bfloat16 v) {
    unsigned short u = *reinterpret_cast<unsigned short*>(&v);
    asm volatile("st.shared.u16 [%0], %1;" :: "r"(addr), "h"(u));
}
__device__ __forceinline__ void sts64(uint32_t addr, uint32_t a, uint32_t b) {
    asm volatile("st.shared.v2.b32 [%0], {%1,%2};" :: "r"(addr), "r"(a), "r"(b));
}
// pack two fp32 -> bf16x2 (lo arg in low half)
__device__ __forceinline__ uint32_t pack_bf2(float lo, float hi) {
    uint32_t r;
    asm("cvt.rn.bf16x2.f32 %0, %1, %2;" : "=r"(r) : "f"(hi), "f"(lo));
    return r;
}

// ---------------------------------------------------------------------------
// Kernel 1: hyper MLP heads (proven — 24us)
// ---------------------------------------------------------------------------
__global__ __launch_bounds__(256) void hyper_kernel(
    const float* __restrict__ z,
    const float* __restrict__ w1, const float* __restrict__ b1,
    const float* __restrict__ w3, const float* __restrict__ b3,
    const float* __restrict__ w4, const float* __restrict__ b4)
{
    extern __shared__ float hs[];
    float* zs   = hs;
    float* w1sT = hs + 4096;
    float* w3sT = hs + 8320;
    float* w4sT = hs + 12544;
    float* h3s  = hs + 14624;

    const int b  = blockIdx.y;
    const int k0 = blockIdx.x * 32;
    const int tid = threadIdx.x;

    #pragma unroll
    for (int i = 0; i < 16; ++i) {
        int f = i * 256 + tid;
        zs[f] = z[((size_t)(b * ZDIM + (f >> 5))) * K_ + k0 + (f & 31)];
    }
    #pragma unroll
    for (int i = 0; i < 16; ++i) {
        int f = i * 256 + tid;
        w1sT[(f & 127) * 33 + (f >> 7)] = w1[f];
    }
    #pragma unroll
    for (int i = 0; i < 16; ++i) {
        int f = i * 256 + tid;
        w3sT[(f & 127) * 33 + (f >> 7)] = w3[f];
    }
    #pragma unroll
    for (int i = 0; i < 8; ++i) {
        int f = i * 256 + tid;
        w4sT[(f & 31) * 65 + (f >> 5)] = w4[f];
    }
    __syncthreads();

    #pragma unroll
    for (int i = 0; i < 4; ++i) {
        int idx = i * 256 + tid;
        int jo = idx & 31, kk = idx >> 5;
        float acc = b1[jo];
        #pragma unroll 8
        for (int j = 0; j < ZDIM; ++j)
            acc += w1sT[j * 33 + jo] * zs[j * 32 + kk];
        g_h1[(size_t)(b * K_ + k0 + kk) * HID_ + jo] = fmaxf(acc, 0.f);
    }
    #pragma unroll
    for (int i = 0; i < 4; ++i) {
        int idx = i * 256 + tid;
        int jo = idx & 31, kk = idx >> 5;
        float acc = b3[jo];
        #pragma unroll 8
        for (int j = 0; j < ZDIM; ++j)
            acc += w3sT[j * 33 + jo] * zs[j * 32 + kk];
        h3s[kk * 32 + jo] = fmaxf(acc, 0.f);
    }
    __syncthreads();

    #pragma unroll
    for (int i = 0; i < 8; ++i) {
        int idx = i * 256 + tid;
        int o = idx & 63, kk = idx >> 6;
        float acc = b4[o];
        #pragma unroll
        for (int j = 0; j < HID_; ++j)
            acc += w4sT[j * 65 + o] * h3s[kk * 32 + j];
        g_bias[(size_t)(b * K_ + k0 + kk) * COUT + o] = acc;
    }
}

// ---------------------------------------------------------------------------
// Kernel 2: weight-gen GEMM — scalar FMA, padded smem (proven core)
// ---------------------------------------------------------------------------
__global__ __launch_bounds__(128) void wgen_kernel(
    const float* __restrict__ w2, const float* __restrict__ b2)
{
    __shared__ float h1sT[HID_ * 68];
    __shared__ float w2sT[HID_ * 132];

    const int rtile = blockIdx.x;
    const int ntile = blockIdx.y;
    const int tid = threadIdx.x;

    const float* hsrc = g_h1 + (size_t)ntile * 64 * HID_;
    #pragma unroll
    for (int i = 0; i < 16; ++i) {
        int f = i * 128 + tid;
        h1sT[(f & 31) * 68 + (f >> 5)] = hsrc[f];
    }
    const float* wsrc = w2 + (size_t)rtile * 128 * HID_;
    #pragma unroll
    for (int i = 0; i < 32; ++i) {
        int f = i * 128 + tid;
        w2sT[(f & 31) * 132 + (f >> 5)] = wsrc[f];
    }
    __syncthreads();

    const int n0 = (tid & 7) * 8;
    const int r0 = (tid >> 3) * 8;

    float acc[8][8];
    #pragma unroll
    for (int a = 0; a < 8; ++a)
        #pragma unroll
        for (int c = 0; c < 8; ++c) acc[a][c] = 0.f;

    #pragma unroll 4
    for (int j = 0; j < HID_; ++j) {
        float4 h0 = *(const float4*)(h1sT + j * 68 + n0);
        float4 h1v = *(const float4*)(h1sT + j * 68 + n0 + 4);
        float4 v0 = *(const float4*)(w2sT + j * 132 + r0);
        float4 v1 = *(const float4*)(w2sT + j * 132 + r0 + 4);
        const float hh[8] = {h0.x, h0.y, h0.z, h0.w, h1v.x, h1v.y, h1v.z, h1v.w};
        const float ww[8] = {v0.x, v0.y, v0.z, v0.w, v1.x, v1.y, v1.z, v1.w};
        #pragma unroll
        for (int a = 0; a < 8; ++a)
            #pragma unroll
            for (int c = 0; c < 8; ++c)
                acc[a][c] += hh[a] * ww[c];
    }

    const int rbase = rtile * 128 + r0;
    float bb[8];
    #pragma unroll
    for (int c = 0; c < 8; ++c) bb[c] = b2[rbase + c];

    #pragma unroll
    for (int a = 0; a < 8; ++a) {
        size_t row = (size_t)(ntile * 64 + n0 + a);
        float* dst = g_weight + row * RTOT + rbase;
        float4 s0 = {acc[a][0] + bb[0], acc[a][1] + bb[1], acc[a][2] + bb[2], acc[a][3] + bb[3]};
        float4 s1 = {acc[a][4] + bb[4], acc[a][5] + bb[5], acc[a][6] + bb[6], acc[a][7] + bb[7]};
        *(float4*)(dst)     = s0;
        *(float4*)(dst + 4) = s1;
    }
}

// ---------------------------------------------------------------------------
// Kernel 3: main GEMM via mma.sync bf16 (HMMA). One CTA per n, block 128.
// A [64s x 128c] (row pad 272B), B [128c x 64o] (row pad 144B).
// 3 passes: AhBh + AlBh + AhBl. Warp grid 2(s) x 2(o); warp = 32s x 32o.
// ---------------------------------------------------------------------------
#define AH_OFF 0u
#define AL_OFF 17408u
#define BH_OFF 34816u
#define BL_OFF 53248u
#define XS_OFF 34816u            // fp32 staging overlays B region (17408 B)
#define SM_MAIN 71680

__global__ __launch_bounds__(128, 3) void main_mma_kernel(
    const float* __restrict__ x, float* __restrict__ out)
{
    extern __shared__ __align__(1024) char smem[];
    const uint32_t sb = smem_u32(smem);
    const int tid  = threadIdx.x;
    const int wid  = tid >> 5;
    const int lane = tid & 31;
    const int n  = blockIdx.x;
    const int b  = n >> 10;
    const int t0 = (n & 1023) * 64;

    const float* xb = x + (size_t)b * CIN * T_ + t0;
    float* Xs = (float*)(smem + XS_OFF);     // [ch][s], stride 68 floats

    // pass1: x -> fp32 staging (coalesced gmem, conflict-light STS.128)
    #pragma unroll
    for (int i = 0; i < 8; ++i) {
        int f = i * 128 + tid;               // 1024 float4 = 64ch x 16
        int ch = f >> 4, sc = (f & 15) * 4;
        float4 v = __ldg((const float4*)(xb + (size_t)ch * T_ + sc));
        *(float4*)(Xs + ch * 68 + sc) = v;
    }
    __syncthreads();

    // pass2: staging -> Ah/Al bf16 [s][c] with shifted channels 64..127
    {
        const int ch   = tid & 63;
        const int part = tid >> 6;           // 0 -> hi, 1 -> lo
        const uint32_t Abase = sb + (part ? AL_OFF : AH_OFF);
        float prev = t0 ? __ldg(xb + (size_t)ch * T_ - 1) : 0.f;
        #pragma unroll
        for (int q = 0; q < 16; ++q) {
            float4 v = *(const float4*)(Xs + ch * 68 + q * 4);
            float e[4] = {v.x, v.y, v.z, v.w};
            #pragma unroll
            for (int j = 0; j < 4; ++j) {
                int s = q * 4 + j;
                float f = e[j];
                __nv_bfloat16 fh = __float2bfloat16_rn(f);
                __nv_bfloat16 ph = __float2bfloat16_rn(prev);
                __nv_bfloat16 cv, pv;
                if (!part) { cv = fh; pv = ph; }
                else {
                    cv = __float2bfloat16_rn(f - __bfloat162float(fh));
                    pv = __float2bfloat16_rn(prev - __bfloat162float(ph));
                }
                sts16(Abase + s * 272 + ch * 2, cv);
                sts16(Abase + s * 272 + (64 + ch) * 2, pv);
                prev = f;
            }
        }
    }
    __syncthreads();   // A-build done reading staging; B may overwrite it now

    // B build: g_weight fp32 [c][o] -> Bh/Bl bf16 [c][o], row pad 144B
    // Tile = 128c x 64o = 8192 floats = 2048 float4 -> 16 iters x 128 threads.
    {
        const float4* wsrc = (const float4*)(g_weight + (size_t)n * RTOT);
        #pragma unroll
        for (int i = 0; i < 16; ++i) {
            int f4 = i * 128 + tid;          // 0..2047 float4
            int c = f4 >> 4, o0 = (f4 & 15) * 4;
            float4 v = __ldg(wsrc + f4);
            uint32_t h0 = pack_bf2(v.x, v.y);
            uint32_t h1 = pack_bf2(v.z, v.w);
            // lo residuals: f - float(bf16(f))
            float r0 = v.x - __uint_as_float(h0 << 16);
            float r1 = v.y - __uint_as_float(h0 & 0xFFFF0000u);
            float r2 = v.z - __uint_as_float(h1 << 16);
            float r3 = v.w - __uint_as_float(h1 & 0xFFFF0000u);
            uint32_t l0 = pack_bf2(r0, r1);
            uint32_t l1 = pack_bf2(r2, r3);
            uint32_t off = (uint32_t)(c * 144 + o0 * 2);
            sts64(sb + BH_OFF + off, h0, h1);
            sts64(sb + BL_OFF + off, l0, l1);
        }
    }
    __syncthreads();

    // ---- MMA mainloop ----
    const int ws = wid & 1;                  // s half
    const int wo = wid >> 1;                 // o half
    const int s_base = ws * 32;
    const int o_base = wo * 32;

    float acc[2][4][4];
    #pragma unroll
    for (int mt = 0; mt < 2; ++mt)
        #pragma unroll
        for (int nt = 0; nt < 4; ++nt)
            #pragma unroll
            for (int r = 0; r < 4; ++r) acc[mt][nt][r] = 0.f;

    const uint32_t a_row   = lane & 15;      // row within 16-row mtile
    const uint32_t a_khalf = lane >> 4;      // 0/1 -> k-cols 0-7 / 8-15
    const uint32_t b_krow  = lane & 15;      // k row within 16 (lanes 0-15 used)

    #pragma unroll
    for (int pass = 0; pass < 3; ++pass) {
        const uint32_t Ab = sb + (pass == 1 ? AL_OFF : AH_OFF);
        const uint32_t Bb = sb + (pass == 2 ? BL_OFF : BH_OFF);
        #pragma unroll
        for (int k = 0; k < 8; ++k) {
            const int k0 = k * 16;
            uint32_t a[2][4];
            #pragma unroll
            for (int mt = 0; mt < 2; ++mt) {
                uint32_t addr = Ab + (s_base + mt * 16 + a_row) * 272
                                   + (k0 + a_khalf * 8) * 2;
                LDSM_X4(a[mt][0], a[mt][1], a[mt][2], a[mt][3], addr);
            }
            uint32_t bf[4][2];
            #pragma unroll
            for (int nt = 0; nt < 4; ++nt) {
                uint32_t addr = Bb + (k0 + b_krow) * 144 + (o_base + nt * 8) * 2;
                LDSM_X2T(bf[nt][0], bf[nt][1], addr);
            }
            #pragma unroll
            for (int mt = 0; mt < 2; ++mt)
                #pragma unroll
                for (int nt = 0; nt < 4; ++nt)
                    MMA16816(acc[mt][nt], a[mt][0], a[mt][1], a[mt][2], a[mt][3],
                             bf[nt][0], bf[nt][1]);
        }
    }

    // ---- epilogue: D frags -> gmem + bias ----
    const int g   = lane >> 2;
    const int tig = lane & 3;
    #pragma unroll
    for (int nt = 0; nt < 4; ++nt) {
        const int o = o_base + nt * 8 + 2 * tig;
        const float bv0 = __ldg(g_bias + (size_t)n * COUT + o);
        const float bv1 = __ldg(g_bias + (size_t)n * COUT + o + 1);
        #pragma unroll
        for (int mt = 0; mt < 2; ++mt) {
            const int s = s_base + mt * 16 + g;
            float* p0 = out + (size_t)(b * COUT + o) * T_ + t0 + s;
            float* p1 = p0 + T_;
            p0[0] = acc[mt][nt][0] + bv0;
            p1[0] = acc[mt][nt][1] + bv1;
            p0[8] = acc[mt][nt][2] + bv0;
            p1[8] = acc[mt][nt][3] + bv1;
        }
    }
}

// ---------------------------------------------------------------------------
extern "C" void kernel_launch(void* const* d_in, const int* in_sizes, int n_in,
                              void* d_out, int out_size)
{
    const float* x  = (const float*)d_in[0];
    const float* z  = (const float*)d_in[1];
    const float* w1 = (const float*)d_in[2];
    const float* b1 = (const float*)d_in[3];
    const float* w2 = (const float*)d_in[4];
    const float* b2 = (const float*)d_in[5];
    const float* w3 = (const float*)d_in[6];
    const float* b3 = (const float*)d_in[7];
    const float* w4 = (const float*)d_in[8];
    const float* b4 = (const float*)d_in[9];
    float* out = (float*)d_out;

    cudaFuncSetAttribute(hyper_kernel,    cudaFuncAttributeMaxDynamicSharedMemorySize, 62592);
    cudaFuncSetAttribute(main_mma_kernel, cudaFuncAttributeMaxDynamicSharedMemorySize, SM_MAIN);

    hyper_kernel<<<dim3(32, 8), 256, 62592>>>(z, w1, b1, w3, b3, w4, b4);
    wgen_kernel<<<dim3(64, 128), 128>>>(w2, b2);
    main_mma_kernel<<<N_, 128, SM_MAIN>>>(x, out);
}

// round 7
// speedup vs baseline: 2.8722x; 2.1402x over previous
#include <cuda_runtime.h>
#include <cuda_fp16.h>
#include <cstdint>

// Problem constants
#define B_   8
#define K_   1024
#define N_   (B_ * K_)
#define S_   64
#define T_   65536
#define CIN  64
#define COUT 64
#define CKS  128
#define HID_ 32
#define ZDIM 128
#define RTOT (CKS * COUT)

// Device scratch
__device__ float  g_h1[N_ * HID_];
__device__ float  g_bias[N_ * COUT];
__device__ __half g_weight[(size_t)N_ * RTOT];   // fp16 [n][r], r = c*64+o

// ---------------------------------------------------------------------------
// PTX helpers
// ---------------------------------------------------------------------------
__device__ __forceinline__ uint32_t smem_u32(const void* p) {
    uint32_t a;
    asm("{ .reg .u64 t; cvta.to.shared.u64 t, %1; cvt.u32.u64 %0, t; }" : "=r"(a) : "l"(p));
    return a;
}
#define LDSM_X4(r0,r1,r2,r3,addr) \
    asm volatile("ldmatrix.sync.aligned.m8n8.x4.shared.b16 {%0,%1,%2,%3}, [%4];" \
        : "=r"(r0),"=r"(r1),"=r"(r2),"=r"(r3) : "r"(addr))
#define LDSM_X2T(r0,r1,addr) \
    asm volatile("ldmatrix.sync.aligned.m8n8.x2.trans.shared.b16 {%0,%1}, [%2];" \
        : "=r"(r0),"=r"(r1) : "r"(addr))
#define MMA16816F(d,a0,a1,a2,a3,b0,b1) \
    asm volatile("mma.sync.aligned.m16n8k16.row.col.f32.f16.f16.f32 " \
        "{%0,%1,%2,%3}, {%4,%5,%6,%7}, {%8,%9}, {%0,%1,%2,%3};" \
        : "+f"((d)[0]),"+f"((d)[1]),"+f"((d)[2]),"+f"((d)[3]) \
        : "r"(a0),"r"(a1),"r"(a2),"r"(a3),"r"(b0),"r"(b1))

__device__ __forceinline__ void sts64(uint32_t addr, uint32_t a, uint32_t b) {
    asm volatile("st.shared.v2.b32 [%0], {%1,%2};" :: "r"(addr), "r"(a), "r"(b));
}
__device__ __forceinline__ uint32_t h2u(__half2 h) {
    return *reinterpret_cast<uint32_t*>(&h);
}

// ---------------------------------------------------------------------------
// Kernel 1: hyper MLP heads (proven)
// ---------------------------------------------------------------------------
__global__ __launch_bounds__(256) void hyper_kernel(
    const float* __restrict__ z,
    const float* __restrict__ w1, const float* __restrict__ b1,
    const float* __restrict__ w3, const float* __restrict__ b3,
    const float* __restrict__ w4, const float* __restrict__ b4)
{
    extern __shared__ float hs[];
    float* zs   = hs;
    float* w1sT = hs + 4096;
    float* w3sT = hs + 8320;
    float* w4sT = hs + 12544;
    float* h3s  = hs + 14624;

    const int b  = blockIdx.y;
    const int k0 = blockIdx.x * 32;
    const int tid = threadIdx.x;

    #pragma unroll
    for (int i = 0; i < 16; ++i) {
        int f = i * 256 + tid;
        zs[f] = z[((size_t)(b * ZDIM + (f >> 5))) * K_ + k0 + (f & 31)];
    }
    #pragma unroll
    for (int i = 0; i < 16; ++i) {
        int f = i * 256 + tid;
        w1sT[(f & 127) * 33 + (f >> 7)] = w1[f];
    }
    #pragma unroll
    for (int i = 0; i < 16; ++i) {
        int f = i * 256 + tid;
        w3sT[(f & 127) * 33 + (f >> 7)] = w3[f];
    }
    #pragma unroll
    for (int i = 0; i < 8; ++i) {
        int f = i * 256 + tid;
        w4sT[(f & 31) * 65 + (f >> 5)] = w4[f];
    }
    __syncthreads();

    #pragma unroll
    for (int i = 0; i < 4; ++i) {
        int idx = i * 256 + tid;
        int jo = idx & 31, kk = idx >> 5;
        float acc = b1[jo];
        #pragma unroll 8
        for (int j = 0; j < ZDIM; ++j)
            acc += w1sT[j * 33 + jo] * zs[j * 32 + kk];
        g_h1[(size_t)(b * K_ + k0 + kk) * HID_ + jo] = fmaxf(acc, 0.f);
    }
    #pragma unroll
    for (int i = 0; i < 4; ++i) {
        int idx = i * 256 + tid;
        int jo = idx & 31, kk = idx >> 5;
        float acc = b3[jo];
        #pragma unroll 8
        for (int j = 0; j < ZDIM; ++j)
            acc += w3sT[j * 33 + jo] * zs[j * 32 + kk];
        h3s[kk * 32 + jo] = fmaxf(acc, 0.f);
    }
    __syncthreads();

    #pragma unroll
    for (int i = 0; i < 8; ++i) {
        int idx = i * 256 + tid;
        int o = idx & 63, kk = idx >> 6;
        float acc = b4[o];
        #pragma unroll
        for (int j = 0; j < HID_; ++j)
            acc += w4sT[j * 65 + o] * h3s[kk * 32 + j];
        g_bias[(size_t)(b * K_ + k0 + kk) * COUT + o] = acc;
    }
}

// ---------------------------------------------------------------------------
// Kernel 2: weight-gen GEMM — scalar FMA core, fp16 output epilogue.
// ---------------------------------------------------------------------------
__global__ __launch_bounds__(128) void wgen_kernel(
    const float* __restrict__ w2, const float* __restrict__ b2)
{
    __shared__ float h1sT[HID_ * 68];
    __shared__ float w2sT[HID_ * 132];

    const int rtile = blockIdx.x;
    const int ntile = blockIdx.y;
    const int tid = threadIdx.x;

    const float* hsrc = g_h1 + (size_t)ntile * 64 * HID_;
    #pragma unroll
    for (int i = 0; i < 16; ++i) {
        int f = i * 128 + tid;
        h1sT[(f & 31) * 68 + (f >> 5)] = hsrc[f];
    }
    const float* wsrc = w2 + (size_t)rtile * 128 * HID_;
    #pragma unroll
    for (int i = 0; i < 32; ++i) {
        int f = i * 128 + tid;
        w2sT[(f & 31) * 132 + (f >> 5)] = wsrc[f];
    }
    __syncthreads();

    const int n0 = (tid & 7) * 8;
    const int r0 = (tid >> 3) * 8;

    float acc[8][8];
    #pragma unroll
    for (int a = 0; a < 8; ++a)
        #pragma unroll
        for (int c = 0; c < 8; ++c) acc[a][c] = 0.f;

    #pragma unroll 4
    for (int j = 0; j < HID_; ++j) {
        float4 h0 = *(const float4*)(h1sT + j * 68 + n0);
        float4 h1v = *(const float4*)(h1sT + j * 68 + n0 + 4);
        float4 v0 = *(const float4*)(w2sT + j * 132 + r0);
        float4 v1 = *(const float4*)(w2sT + j * 132 + r0 + 4);
        const float hh[8] = {h0.x, h0.y, h0.z, h0.w, h1v.x, h1v.y, h1v.z, h1v.w};
        const float ww[8] = {v0.x, v0.y, v0.z, v0.w, v1.x, v1.y, v1.z, v1.w};
        #pragma unroll
        for (int a = 0; a < 8; ++a)
            #pragma unroll
            for (int c = 0; c < 8; ++c)
                acc[a][c] += hh[a] * ww[c];
    }

    const int rbase = rtile * 128 + r0;
    float bb[8];
    #pragma unroll
    for (int c = 0; c < 8; ++c) bb[c] = b2[rbase + c];

    #pragma unroll
    for (int a = 0; a < 8; ++a) {
        size_t row = (size_t)(ntile * 64 + n0 + a);
        __half* dst = g_weight + row * RTOT + rbase;
        uint4 v;
        v.x = h2u(__floats2half2_rn(acc[a][0] + bb[0], acc[a][1] + bb[1]));
        v.y = h2u(__floats2half2_rn(acc[a][2] + bb[2], acc[a][3] + bb[3]));
        v.z = h2u(__floats2half2_rn(acc[a][4] + bb[4], acc[a][5] + bb[5]));
        v.w = h2u(__floats2half2_rn(acc[a][6] + bb[6], acc[a][7] + bb[7]));
        *(uint4*)dst = v;
    }
}

// ---------------------------------------------------------------------------
// Kernel 3: main GEMM via mma.sync fp16, SINGLE pass. One CTA per n, block 128.
// A fp16 [sp][ch]: sp=0..64 holds x[t0+sp-1], 64 ch, row stride 176B.
//   kstep k<4  (c = ch      ): A row = s+1  (unshifted tap)
//   kstep k>=4 (c = ch + 64 ): A row = s    (shifted tap)
// B fp16 [c][o], 128 rows x 144B (direct copy of fp16 g_weight).
// Region0 (18432B) = fp32 staging Xs[64][68] + P[64]  ->  overlaid by B.
// ---------------------------------------------------------------------------
#define P_OFF   17408u
#define A_OFF   18432u
#define A_STR   176
#define SM_MAIN (18432 + 65 * 176)   // 29872 B

__global__ __launch_bounds__(128) void main_mma_kernel(
    const float* __restrict__ x, float* __restrict__ out)
{
    extern __shared__ __align__(1024) char smem[];
    const uint32_t sb = smem_u32(smem);
    const int tid  = threadIdx.x;
    const int wid  = tid >> 5;
    const int lane = tid & 31;
    const int n  = blockIdx.x;
    const int b  = n >> 10;
    const int t0 = (n & 1023) * 64;

    const float* xb = x + (size_t)b * CIN * T_ + t0;
    float* Xs = (float*)smem;                 // [ch][s], stride 68 floats
    float* P  = (float*)(smem + P_OFF);       // prev sample per ch

    // early B prefetch (fp16 weights, 16KB = 1024 uint4)
    const uint4* wsrc = (const uint4*)(g_weight + (size_t)n * RTOT);
    uint4 wreg[8];
    #pragma unroll
    for (int i = 0; i < 8; ++i) wreg[i] = __ldg(wsrc + i * 128 + tid);

    // pass1: x -> fp32 staging
    #pragma unroll
    for (int i = 0; i < 8; ++i) {
        int f = i * 128 + tid;                // 1024 float4 = 64ch x 16
        int ch = f >> 4, sc = (f & 15) * 4;
        float4 v = __ldg((const float4*)(xb + (size_t)ch * T_ + sc));
        *(float4*)(Xs + ch * 68 + sc) = v;
    }
    if (tid < 64) P[tid] = t0 ? __ldg(xb + (size_t)tid * T_ - 1) : 0.f;
    __syncthreads();

    // A-build: fp16 [sp][ch]. Row 0 from P; rows 1..64 from staging (transpose).
    if (tid < 16) {
        float4 p = *(const float4*)(P + tid * 4);
        sts64(sb + A_OFF + tid * 8,
              h2u(__floats2half2_rn(p.x, p.y)), h2u(__floats2half2_rn(p.z, p.w)));
    }
    #pragma unroll
    for (int i = 0; i < 8; ++i) {
        int idx = i * 128 + tid;              // 1024 quads
        int sp  = (idx & 63) + 1;             // 1..64  (lane-consecutive: no LDS conflicts)
        int chg = idx >> 6;                   // 0..15
        const float* xs = Xs + chg * 4 * 68 + (sp - 1);
        float e0 = xs[0], e1 = xs[68], e2 = xs[136], e3 = xs[204];
        sts64(sb + A_OFF + sp * A_STR + chg * 8,
              h2u(__floats2half2_rn(e0, e1)), h2u(__floats2half2_rn(e2, e3)));
    }
    __syncthreads();

    // B-build: straight copy to [c][o] stride 144B (overlays staging)
    #pragma unroll
    for (int i = 0; i < 8; ++i) {
        int f4 = i * 128 + tid;               // 0..1023
        int c = f4 >> 3, o0 = (f4 & 7) * 8;
        *(uint4*)(smem + c * 144 + o0 * 2) = wreg[i];
    }
    __syncthreads();

    // ---- MMA mainloop: 1 pass, 8 ksteps ----
    const int s_base = (wid & 1) * 32;
    const int o_base = (wid >> 1) * 32;

    float acc[2][4][4];
    #pragma unroll
    for (int mt = 0; mt < 2; ++mt)
        #pragma unroll
        for (int nt = 0; nt < 4; ++nt)
            #pragma unroll
            for (int r = 0; r < 4; ++r) acc[mt][nt][r] = 0.f;

    const uint32_t a_row = lane & 15;
    const uint32_t a_kh  = lane >> 4;
    const uint32_t b_kr  = lane & 15;

    #pragma unroll
    for (int k = 0; k < 8; ++k) {
        const int rowoff = (k < 4) ? 1 : 0;
        const int chcol  = (k & 3) * 16;
        uint32_t a[2][4];
        #pragma unroll
        for (int mt = 0; mt < 2; ++mt) {
            uint32_t addr = sb + A_OFF
                          + (rowoff + s_base + mt * 16 + a_row) * A_STR
                          + (chcol + a_kh * 8) * 2;
            LDSM_X4(a[mt][0], a[mt][1], a[mt][2], a[mt][3], addr);
        }
        uint32_t bf[4][2];
        #pragma unroll
        for (int nt = 0; nt < 4; ++nt) {
            uint32_t addr = sb + (k * 16 + b_kr) * 144 + (o_base + nt * 8) * 2;
            LDSM_X2T(bf[nt][0], bf[nt][1], addr);
        }
        #pragma unroll
        for (int mt = 0; mt < 2; ++mt)
            #pragma unroll
            for (int nt = 0; nt < 4; ++nt)
                MMA16816F(acc[mt][nt], a[mt][0], a[mt][1], a[mt][2], a[mt][3],
                          bf[nt][0], bf[nt][1]);
    }

    // ---- epilogue: D frags -> gmem + bias (layout proven in R5) ----
    const int g   = lane >> 2;
    const int tig = lane & 3;
    #pragma unroll
    for (int nt = 0; nt < 4; ++nt) {
        const int o = o_base + nt * 8 + 2 * tig;
        const float bv0 = __ldg(g_bias + (size_t)n * COUT + o);
        const float bv1 = __ldg(g_bias + (size_t)n * COUT + o + 1);
        #pragma unroll
        for (int mt = 0; mt < 2; ++mt) {
            const int s = s_base + mt * 16 + g;
            float* p0 = out + (size_t)(b * COUT + o) * T_ + t0 + s;
            float* p1 = p0 + T_;
            p0[0] = acc[mt][nt][0] + bv0;
            p1[0] = acc[mt][nt][1] + bv1;
            p0[8] = acc[mt][nt][2] + bv0;
            p1[8] = acc[mt][nt][3] + bv1;
        }
    }
}

// ---------------------------------------------------------------------------
extern "C" void kernel_launch(void* const* d_in, const int* in_sizes, int n_in,
                              void* d_out, int out_size)
{
    const float* x  = (const float*)d_in[0];
    const float* z  = (const float*)d_in[1];
    const float* w1 = (const float*)d_in[2];
    const float* b1 = (const float*)d_in[3];
    const float* w2 = (const float*)d_in[4];
    const float* b2 = (const float*)d_in[5];
    const float* w3 = (const float*)d_in[6];
    const float* b3 = (const float*)d_in[7];
    const float* w4 = (const float*)d_in[8];
    const float* b4 = (const float*)d_in[9];
    float* out = (float*)d_out;

    cudaFuncSetAttribute(hyper_kernel,    cudaFuncAttributeMaxDynamicSharedMemorySize, 62592);
    cudaFuncSetAttribute(main_mma_kernel, cudaFuncAttributeMaxDynamicSharedMemorySize, SM_MAIN);

    hyper_kernel<<<dim3(32, 8), 256, 62592>>>(z, w1, b1, w3, b3, w4, b4);
    wgen_kernel<<<dim3(64, 128), 128>>>(w2, b2);
    main_mma_kernel<<<N_, 128, SM_MAIN>>>(x, out);
}

// round 8
// speedup vs baseline: 4.6696x; 1.6258x over previous
#include <cuda_runtime.h>
#include <cuda_fp16.h>
#include <cstdint>

// Problem constants
#define B_   8
#define K_   1024
#define N_   (B_ * K_)
#define S_   64
#define T_   65536
#define CIN  64
#define COUT 64
#define CKS  128
#define HID_ 32
#define ZDIM 128
#define RTOT (CKS * COUT)

// Device scratch
__device__ __half g_h1h[N_ * HID_];              // fp16 [n][j]
__device__ float  g_bias[N_ * COUT];
__device__ __half g_weight[(size_t)N_ * RTOT];   // fp16 [n][r], r = c*64+o

// ---------------------------------------------------------------------------
// PTX helpers
// ---------------------------------------------------------------------------
__device__ __forceinline__ uint32_t smem_u32(const void* p) {
    uint32_t a;
    asm("{ .reg .u64 t; cvta.to.shared.u64 t, %1; cvt.u32.u64 %0, t; }" : "=r"(a) : "l"(p));
    return a;
}
#define LDSM_X4(r0,r1,r2,r3,addr) \
    asm volatile("ldmatrix.sync.aligned.m8n8.x4.shared.b16 {%0,%1,%2,%3}, [%4];" \
        : "=r"(r0),"=r"(r1),"=r"(r2),"=r"(r3) : "r"(addr))
#define LDSM_X2(r0,r1,addr) \
    asm volatile("ldmatrix.sync.aligned.m8n8.x2.shared.b16 {%0,%1}, [%2];" \
        : "=r"(r0),"=r"(r1) : "r"(addr))
#define LDSM_X2T(r0,r1,addr) \
    asm volatile("ldmatrix.sync.aligned.m8n8.x2.trans.shared.b16 {%0,%1}, [%2];" \
        : "=r"(r0),"=r"(r1) : "r"(addr))
#define MMA16816F(d,a0,a1,a2,a3,b0,b1) \
    asm volatile("mma.sync.aligned.m16n8k16.row.col.f32.f16.f16.f32 " \
        "{%0,%1,%2,%3}, {%4,%5,%6,%7}, {%8,%9}, {%0,%1,%2,%3};" \
        : "+f"((d)[0]),"+f"((d)[1]),"+f"((d)[2]),"+f"((d)[3]) \
        : "r"(a0),"r"(a1),"r"(a2),"r"(a3),"r"(b0),"r"(b1))

__device__ __forceinline__ void sts64(uint32_t addr, uint32_t a, uint32_t b) {
    asm volatile("st.shared.v2.b32 [%0], {%1,%2};" :: "r"(addr), "r"(a), "r"(b));
}
__device__ __forceinline__ uint32_t h2u(__half2 h) {
    return *reinterpret_cast<uint32_t*>(&h);
}

// ---------------------------------------------------------------------------
// Kernel 1: hyper MLP heads — register-blocked (4/8 outputs per weight load)
// grid (32 ktiles, 8 b), block 256. h1 emitted in fp16 for HMMA wgen.
// ---------------------------------------------------------------------------
__global__ __launch_bounds__(256) void hyper_kernel(
    const float* __restrict__ z,
    const float* __restrict__ w1, const float* __restrict__ b1,
    const float* __restrict__ w3, const float* __restrict__ b3,
    const float* __restrict__ w4, const float* __restrict__ b4)
{
    extern __shared__ float hs[];
    float* zs   = hs;            // [j][kk] 128x32      = 4096
    float* w1sT = hs + 4096;     // [j][jo] 128x33      = 4224
    float* w3sT = hs + 8320;     //                      4224
    float* w4sT = hs + 12544;    // [j][o]  32x65       = 2080
    float* h3s  = hs + 14624;    // [kk][jo] 32x33      = 1056

    const int b  = blockIdx.y;
    const int k0 = blockIdx.x * 32;
    const int tid = threadIdx.x;

    #pragma unroll
    for (int i = 0; i < 16; ++i) {
        int f = i * 256 + tid;
        zs[f] = z[((size_t)(b * ZDIM + (f >> 5))) * K_ + k0 + (f & 31)];
    }
    #pragma unroll
    for (int i = 0; i < 16; ++i) {
        int f = i * 256 + tid;
        w1sT[(f & 127) * 33 + (f >> 7)] = w1[f];
    }
    #pragma unroll
    for (int i = 0; i < 16; ++i) {
        int f = i * 256 + tid;
        w3sT[(f & 127) * 33 + (f >> 7)] = w3[f];
    }
    #pragma unroll
    for (int i = 0; i < 8; ++i) {
        int f = i * 256 + tid;
        w4sT[(f & 31) * 65 + (f >> 5)] = w4[f];
    }
    __syncthreads();

    // h1 + h3: thread = (jo, kkg); 4 kk per thread
    {
        const int jo  = tid & 31;
        const int kkg = tid >> 5;            // 0..7
        float a1[4] = {b1[jo], b1[jo], b1[jo], b1[jo]};
        float a3[4] = {b3[jo], b3[jo], b3[jo], b3[jo]};
        #pragma unroll 8
        for (int j = 0; j < ZDIM; ++j) {
            float4 zv = *(const float4*)(zs + j * 32 + kkg * 4);
            float wa = w1sT[j * 33 + jo];
            float wb = w3sT[j * 33 + jo];
            a1[0] += wa * zv.x; a1[1] += wa * zv.y; a1[2] += wa * zv.z; a1[3] += wa * zv.w;
            a3[0] += wb * zv.x; a3[1] += wb * zv.y; a3[2] += wb * zv.z; a3[3] += wb * zv.w;
        }
        #pragma unroll
        for (int u = 0; u < 4; ++u) {
            int kk = kkg * 4 + u;
            g_h1h[(size_t)(b * K_ + k0 + kk) * HID_ + jo] =
                __float2half(fmaxf(a1[u], 0.f));
            h3s[kk * 33 + jo] = fmaxf(a3[u], 0.f);
        }
    }
    __syncthreads();

    // bias: thread = (o, kg); 8 kk per thread
    {
        const int o  = tid & 63;
        const int kg = tid >> 6;             // 0..3
        float ab[8];
        float bv = b4[o];
        #pragma unroll
        for (int u = 0; u < 8; ++u) ab[u] = bv;
        #pragma unroll
        for (int j = 0; j < HID_; ++j) {
            float w = w4sT[j * 65 + o];
            #pragma unroll
            for (int u = 0; u < 8; ++u)
                ab[u] += w * h3s[(kg * 8 + u) * 33 + j];
        }
        #pragma unroll
        for (int u = 0; u < 8; ++u)
            g_bias[(size_t)(b * K_ + k0 + kg * 8 + u) * COUT + o] = ab[u];
    }
}

// ---------------------------------------------------------------------------
// Kernel 2: weight-gen via mma.sync fp16. grid (64 rtiles, 64 ntiles), blk 256.
// D[128n x 128r] = h1[128n x 32j] @ w2T[32j x 128r] + b2.
// A smem [n][j] / B smem [r][j], both 80B rows (conflict-free ldmatrix).
// Warp grid 2(n) x 4(r): warp tile 64n x 32r. K=32 -> 2 ksteps.
// ---------------------------------------------------------------------------
__global__ __launch_bounds__(256) void wgen_kernel(
    const float* __restrict__ w2, const float* __restrict__ b2)
{
    __shared__ __align__(16) __half Ah[128 * 40];   // 10240 B
    __shared__ __align__(16) __half Bh[128 * 40];   // 10240 B

    const int rtile = blockIdx.x;
    const int ntile = blockIdx.y;
    const int tid  = threadIdx.x;
    const int wid  = tid >> 5;
    const int lane = tid & 31;

    // A: fp16 h1 tile, 512 uint4
    const uint4* hsrc = (const uint4*)(g_h1h + (size_t)ntile * 128 * HID_);
    #pragma unroll
    for (int i = 0; i < 2; ++i) {
        int q = i * 256 + tid;               // 0..511
        int n = q >> 2, jq = q & 3;
        *(uint4*)&Ah[n * 40 + jq * 8] = __ldg(hsrc + q);
    }
    // B: w2 fp32 [r][j] -> fp16, 1024 float4
    const float4* wsrc = (const float4*)(w2 + (size_t)rtile * 128 * HID_);
    #pragma unroll
    for (int i = 0; i < 4; ++i) {
        int q = i * 256 + tid;               // 0..1023
        int r = q >> 3, jq = q & 7;
        float4 v = __ldg(wsrc + q);
        uint32_t p0 = h2u(__floats2half2_rn(v.x, v.y));
        uint32_t p1 = h2u(__floats2half2_rn(v.z, v.w));
        sts64(smem_u32(&Bh[r * 40 + jq * 4]), p0, p1);
    }
    __syncthreads();

    const uint32_t sbA = smem_u32(Ah);
    const uint32_t sbB = smem_u32(Bh);
    const int nb = (wid & 1) * 64;
    const int rb = (wid >> 1) * 32;

    float acc[4][4][4];
    #pragma unroll
    for (int mt = 0; mt < 4; ++mt)
        #pragma unroll
        for (int nt = 0; nt < 4; ++nt)
            #pragma unroll
            for (int u = 0; u < 4; ++u) acc[mt][nt][u] = 0.f;

    const int a_row = lane & 15;
    const int a_kh  = lane >> 4;
    const int b_row = lane & 7;
    const int b_ks  = (lane >> 3) & 1;

    #pragma unroll
    for (int ks = 0; ks < 2; ++ks) {
        const int k0 = ks * 16;
        uint32_t a[4][4];
        #pragma unroll
        for (int mt = 0; mt < 4; ++mt) {
            uint32_t addr = sbA + (nb + mt * 16 + a_row) * 80 + (k0 + a_kh * 8) * 2;
            LDSM_X4(a[mt][0], a[mt][1], a[mt][2], a[mt][3], addr);
        }
        uint32_t bf[4][2];
        #pragma unroll
        for (int nt = 0; nt < 4; ++nt) {
            uint32_t addr = sbB + (rb + nt * 8 + b_row) * 80 + (k0 + b_ks * 8) * 2;
            LDSM_X2(bf[nt][0], bf[nt][1], addr);
        }
        #pragma unroll
        for (int mt = 0; mt < 4; ++mt)
            #pragma unroll
            for (int nt = 0; nt < 4; ++nt)
                MMA16816F(acc[mt][nt], a[mt][0], a[mt][1], a[mt][2], a[mt][3],
                          bf[nt][0], bf[nt][1]);
    }

    // epilogue: + b2, fp16 pairs to g_weight
    const int g   = lane >> 2;
    const int tig = lane & 3;
    #pragma unroll
    for (int nt = 0; nt < 4; ++nt) {
        const int r = rtile * 128 + rb + nt * 8 + tig * 2;
        const float bv0 = __ldg(b2 + r);
        const float bv1 = __ldg(b2 + r + 1);
        #pragma unroll
        for (int mt = 0; mt < 4; ++mt) {
            const size_t n0 = (size_t)(ntile * 128 + nb + mt * 16 + g);
            *(__half2*)(g_weight + n0 * RTOT + r) =
                __floats2half2_rn(acc[mt][nt][0] + bv0, acc[mt][nt][1] + bv1);
            *(__half2*)(g_weight + (n0 + 8) * RTOT + r) =
                __floats2half2_rn(acc[mt][nt][2] + bv0, acc[mt][nt][3] + bv1);
        }
    }
}

// ---------------------------------------------------------------------------
// Kernel 3: main GEMM via mma.sync fp16, single pass (proven R6). blk 128.
// ---------------------------------------------------------------------------
#define P_OFF   17408u
#define A_OFF   18432u
#define A_STR   176
#define SM_MAIN (18432 + 65 * 176)   // 29872 B

__global__ __launch_bounds__(128) void main_mma_kernel(
    const float* __restrict__ x, float* __restrict__ out)
{
    extern __shared__ __align__(1024) char smem[];
    const uint32_t sb = smem_u32(smem);
    const int tid  = threadIdx.x;
    const int wid  = tid >> 5;
    const int lane = tid & 31;
    const int n  = blockIdx.x;
    const int b  = n >> 10;
    const int t0 = (n & 1023) * 64;

    const float* xb = x + (size_t)b * CIN * T_ + t0;
    float* Xs = (float*)smem;                 // [ch][s], stride 68 floats
    float* P  = (float*)(smem + P_OFF);

    const uint4* wsrc = (const uint4*)(g_weight + (size_t)n * RTOT);
    uint4 wreg[8];
    #pragma unroll
    for (int i = 0; i < 8; ++i) wreg[i] = __ldg(wsrc + i * 128 + tid);

    #pragma unroll
    for (int i = 0; i < 8; ++i) {
        int f = i * 128 + tid;
        int ch = f >> 4, sc = (f & 15) * 4;
        float4 v = __ldg((const float4*)(xb + (size_t)ch * T_ + sc));
        *(float4*)(Xs + ch * 68 + sc) = v;
    }
    if (tid < 64) P[tid] = t0 ? __ldg(xb + (size_t)tid * T_ - 1) : 0.f;
    __syncthreads();

    if (tid < 16) {
        float4 p = *(const float4*)(P + tid * 4);
        sts64(sb + A_OFF + tid * 8,
              h2u(__floats2half2_rn(p.x, p.y)), h2u(__floats2half2_rn(p.z, p.w)));
    }
    #pragma unroll
    for (int i = 0; i < 8; ++i) {
        int idx = i * 128 + tid;
        int sp  = (idx & 63) + 1;
        int chg = idx >> 6;
        const float* xs = Xs + chg * 4 * 68 + (sp - 1);
        float e0 = xs[0], e1 = xs[68], e2 = xs[136], e3 = xs[204];
        sts64(sb + A_OFF + sp * A_STR + chg * 8,
              h2u(__floats2half2_rn(e0, e1)), h2u(__floats2half2_rn(e2, e3)));
    }
    __syncthreads();

    #pragma unroll
    for (int i = 0; i < 8; ++i) {
        int f4 = i * 128 + tid;
        int c = f4 >> 3, o0 = (f4 & 7) * 8;
        *(uint4*)(smem + c * 144 + o0 * 2) = wreg[i];
    }
    __syncthreads();

    const int s_base = (wid & 1) * 32;
    const int o_base = (wid >> 1) * 32;

    float acc[2][4][4];
    #pragma unroll
    for (int mt = 0; mt < 2; ++mt)
        #pragma unroll
        for (int nt = 0; nt < 4; ++nt)
            #pragma unroll
            for (int r = 0; r < 4; ++r) acc[mt][nt][r] = 0.f;

    const uint32_t a_row = lane & 15;
    const uint32_t a_kh  = lane >> 4;
    const uint32_t b_kr  = lane & 15;

    #pragma unroll
    for (int k = 0; k < 8; ++k) {
        const int rowoff = (k < 4) ? 1 : 0;
        const int chcol  = (k & 3) * 16;
        uint32_t a[2][4];
        #pragma unroll
        for (int mt = 0; mt < 2; ++mt) {
            uint32_t addr = sb + A_OFF
                          + (rowoff + s_base + mt * 16 + a_row) * A_STR
                          + (chcol + a_kh * 8) * 2;
            LDSM_X4(a[mt][0], a[mt][1], a[mt][2], a[mt][3], addr);
        }
        uint32_t bf[4][2];
        #pragma unroll
        for (int nt = 0; nt < 4; ++nt) {
            uint32_t addr = sb + (k * 16 + b_kr) * 144 + (o_base + nt * 8) * 2;
            LDSM_X2T(bf[nt][0], bf[nt][1], addr);
        }
        #pragma unroll
        for (int mt = 0; mt < 2; ++mt)
            #pragma unroll
            for (int nt = 0; nt < 4; ++nt)
                MMA16816F(acc[mt][nt], a[mt][0], a[mt][1], a[mt][2], a[mt][3],
                          bf[nt][0], bf[nt][1]);
    }

    const int g   = lane >> 2;
    const int tig = lane & 3;
    #pragma unroll
    for (int nt = 0; nt < 4; ++nt) {
        const int o = o_base + nt * 8 + 2 * tig;
        const float bv0 = __ldg(g_bias + (size_t)n * COUT + o);
        const float bv1 = __ldg(g_bias + (size_t)n * COUT + o + 1);
        #pragma unroll
        for (int mt = 0; mt < 2; ++mt) {
            const int s = s_base + mt * 16 + g;
            float* p0 = out + (size_t)(b * COUT + o) * T_ + t0 + s;
            float* p1 = p0 + T_;
            p0[0] = acc[mt][nt][0] + bv0;
            p1[0] = acc[mt][nt][1] + bv1;
            p0[8] = acc[mt][nt][2] + bv0;
            p1[8] = acc[mt][nt][3] + bv1;
        }
    }
}

// ---------------------------------------------------------------------------
extern "C" void kernel_launch(void* const* d_in, const int* in_sizes, int n_in,
                              void* d_out, int out_size)
{
    const float* x  = (const float*)d_in[0];
    const float* z  = (const float*)d_in[1];
    const float* w1 = (const float*)d_in[2];
    const float* b1 = (const float*)d_in[3];
    const float* w2 = (const float*)d_in[4];
    const float* b2 = (const float*)d_in[5];
    const float* w3 = (const float*)d_in[6];
    const float* b3 = (const float*)d_in[7];
    const float* w4 = (const float*)d_in[8];
    const float* b4 = (const float*)d_in[9];
    float* out = (float*)d_out;

    cudaFuncSetAttribute(hyper_kernel,    cudaFuncAttributeMaxDynamicSharedMemorySize, 62720);
    cudaFuncSetAttribute(main_mma_kernel, cudaFuncAttributeMaxDynamicSharedMemorySize, SM_MAIN);

    hyper_kernel<<<dim3(32, 8), 256, 62720>>>(z, w1, b1, w3, b3, w4, b4);
    wgen_kernel<<<dim3(64, 64), 256>>>(w2, b2);
    main_mma_kernel<<<N_, 128, SM_MAIN>>>(x, out);
}

// round 11
// speedup vs baseline: 4.6803x; 1.0023x over previous
#include <cuda_runtime.h>
#include <cuda_fp16.h>
#include <cstdint>

// Problem constants
#define B_   8
#define K_   1024
#define N_   (B_ * K_)
#define S_   64
#define T_   65536
#define CIN  64
#define COUT 64
#define CKS  128
#define HID_ 32
#define ZDIM 128
#define RTOT (CKS * COUT)

// Device scratch
__device__ __half g_h1h[N_ * HID_];              // fp16 [n][j]
__device__ float  g_bias[N_ * COUT];
__device__ __half g_weight[(size_t)N_ * RTOT];   // fp16 [n][r], r = c*64+o

// ---------------------------------------------------------------------------
// PTX helpers
// ---------------------------------------------------------------------------
__device__ __forceinline__ uint32_t smem_u32(const void* p) {
    uint32_t a;
    asm("{ .reg .u64 t; cvta.to.shared.u64 t, %1; cvt.u32.u64 %0, t; }" : "=r"(a) : "l"(p));
    return a;
}
#define LDSM_X4(r0,r1,r2,r3,addr) \
    asm volatile("ldmatrix.sync.aligned.m8n8.x4.shared.b16 {%0,%1,%2,%3}, [%4];" \
        : "=r"(r0),"=r"(r1),"=r"(r2),"=r"(r3) : "r"(addr))
#define LDSM_X2(r0,r1,addr) \
    asm volatile("ldmatrix.sync.aligned.m8n8.x2.shared.b16 {%0,%1}, [%2];" \
        : "=r"(r0),"=r"(r1) : "r"(addr))
#define LDSM_X2T(r0,r1,addr) \
    asm volatile("ldmatrix.sync.aligned.m8n8.x2.trans.shared.b16 {%0,%1}, [%2];" \
        : "=r"(r0),"=r"(r1) : "r"(addr))
#define MMA16816F(d,a0,a1,a2,a3,b0,b1) \
    asm volatile("mma.sync.aligned.m16n8k16.row.col.f32.f16.f16.f32 " \
        "{%0,%1,%2,%3}, {%4,%5,%6,%7}, {%8,%9}, {%0,%1,%2,%3};" \
        : "+f"((d)[0]),"+f"((d)[1]),"+f"((d)[2]),"+f"((d)[3]) \
        : "r"(a0),"r"(a1),"r"(a2),"r"(a3),"r"(b0),"r"(b1))

__device__ __forceinline__ void sts64(uint32_t addr, uint32_t a, uint32_t b) {
    asm volatile("st.shared.v2.b32 [%0], {%1,%2};" :: "r"(addr), "r"(a), "r"(b));
}
__device__ __forceinline__ uint32_t h2u(__half2 h) {
    return *reinterpret_cast<uint32_t*>(&h);
}

// ---------------------------------------------------------------------------
// Kernel 1: hyper MLP heads — register-blocked (proven, 12us)
// ---------------------------------------------------------------------------
__global__ __launch_bounds__(256) void hyper_kernel(
    const float* __restrict__ z,
    const float* __restrict__ w1, const float* __restrict__ b1,
    const float* __restrict__ w3, const float* __restrict__ b3,
    const float* __restrict__ w4, const float* __restrict__ b4)
{
    extern __shared__ float hs[];
    float* zs   = hs;
    float* w1sT = hs + 4096;
    float* w3sT = hs + 8320;
    float* w4sT = hs + 12544;
    float* h3s  = hs + 14624;

    const int b  = blockIdx.y;
    const int k0 = blockIdx.x * 32;
    const int tid = threadIdx.x;

    #pragma unroll
    for (int i = 0; i < 16; ++i) {
        int f = i * 256 + tid;
        zs[f] = z[((size_t)(b * ZDIM + (f >> 5))) * K_ + k0 + (f & 31)];
    }
    #pragma unroll
    for (int i = 0; i < 16; ++i) {
        int f = i * 256 + tid;
        w1sT[(f & 127) * 33 + (f >> 7)] = w1[f];
    }
    #pragma unroll
    for (int i = 0; i < 16; ++i) {
        int f = i * 256 + tid;
        w3sT[(f & 127) * 33 + (f >> 7)] = w3[f];
    }
    #pragma unroll
    for (int i = 0; i < 8; ++i) {
        int f = i * 256 + tid;
        w4sT[(f & 31) * 65 + (f >> 5)] = w4[f];
    }
    __syncthreads();

    {
        const int jo  = tid & 31;
        const int kkg = tid >> 5;
        float a1[4] = {b1[jo], b1[jo], b1[jo], b1[jo]};
        float a3[4] = {b3[jo], b3[jo], b3[jo], b3[jo]};
        #pragma unroll 8
        for (int j = 0; j < ZDIM; ++j) {
            float4 zv = *(const float4*)(zs + j * 32 + kkg * 4);
            float wa = w1sT[j * 33 + jo];
            float wb = w3sT[j * 33 + jo];
            a1[0] += wa * zv.x; a1[1] += wa * zv.y; a1[2] += wa * zv.z; a1[3] += wa * zv.w;
            a3[0] += wb * zv.x; a3[1] += wb * zv.y; a3[2] += wb * zv.z; a3[3] += wb * zv.w;
        }
        #pragma unroll
        for (int u = 0; u < 4; ++u) {
            int kk = kkg * 4 + u;
            g_h1h[(size_t)(b * K_ + k0 + kk) * HID_ + jo] =
                __float2half(fmaxf(a1[u], 0.f));
            h3s[kk * 33 + jo] = fmaxf(a3[u], 0.f);
        }
    }
    __syncthreads();

    {
        const int o  = tid & 63;
        const int kg = tid >> 6;
        float ab[8];
        float bv = b4[o];
        #pragma unroll
        for (int u = 0; u < 8; ++u) ab[u] = bv;
        #pragma unroll
        for (int j = 0; j < HID_; ++j) {
            float w = w4sT[j * 65 + o];
            #pragma unroll
            for (int u = 0; u < 8; ++u)
                ab[u] += w * h3s[(kg * 8 + u) * 33 + j];
        }
        #pragma unroll
        for (int u = 0; u < 8; ++u)
            g_bias[(size_t)(b * K_ + k0 + kg * 8 + u) * COUT + o] = ab[u];
    }
}

// ---------------------------------------------------------------------------
// Kernel 2: weight-gen via mma.sync fp16 + smem-staged coalesced epilogue.
// grid (64 rtiles, 64 ntiles), blk 256. D[128n x 128r].
// D staging rows: 136 halfs (272B) -> frag-store banks 4g+tig (conflict-free),
// stream-out 2048 uint4 (128 rows x 16 uint4) fully coalesced.
// ---------------------------------------------------------------------------
#define D_STR 136   // halfs per D row (272 B), holds 128 r + 8 pad

__global__ __launch_bounds__(256) void wgen_kernel(
    const float* __restrict__ w2, const float* __restrict__ b2)
{
    __shared__ __align__(16) char wsm[128 * D_STR * 2];  // 34816 B (D); Ah+Bh overlap
    __half* Ah = (__half*)wsm;                      // [n][j] 80B rows, 10240 B
    __half* Bh = (__half*)(wsm + 10240);            // [r][j] 80B rows, 10240 B

    const int rtile = blockIdx.x;
    const int ntile = blockIdx.y;
    const int tid  = threadIdx.x;
    const int wid  = tid >> 5;
    const int lane = tid & 31;

    // A: fp16 h1 tile, 512 uint4
    const uint4* hsrc = (const uint4*)(g_h1h + (size_t)ntile * 128 * HID_);
    #pragma unroll
    for (int i = 0; i < 2; ++i) {
        int q = i * 256 + tid;
        int n = q >> 2, jq = q & 3;
        *(uint4*)&Ah[n * 40 + jq * 8] = __ldg(hsrc + q);
    }
    // B: w2 fp32 [r][j] -> fp16
    const float4* wsrc = (const float4*)(w2 + (size_t)rtile * 128 * HID_);
    #pragma unroll
    for (int i = 0; i < 4; ++i) {
        int q = i * 256 + tid;
        int r = q >> 3, jq = q & 7;
        float4 v = __ldg(wsrc + q);
        uint32_t p0 = h2u(__floats2half2_rn(v.x, v.y));
        uint32_t p1 = h2u(__floats2half2_rn(v.z, v.w));
        sts64(smem_u32(&Bh[r * 40 + jq * 4]), p0, p1);
    }
    __syncthreads();

    const uint32_t sbA = smem_u32(Ah);
    const uint32_t sbB = smem_u32(Bh);
    const int nb = (wid & 1) * 64;
    const int rb = (wid >> 1) * 32;

    float acc[4][4][4];
    #pragma unroll
    for (int mt = 0; mt < 4; ++mt)
        #pragma unroll
        for (int nt = 0; nt < 4; ++nt)
            #pragma unroll
            for (int u = 0; u < 4; ++u) acc[mt][nt][u] = 0.f;

    const int a_row = lane & 15;
    const int a_kh  = lane >> 4;
    const int b_row = lane & 7;
    const int b_ks  = (lane >> 3) & 1;

    #pragma unroll
    for (int ks = 0; ks < 2; ++ks) {
        const int k0 = ks * 16;
        uint32_t a[4][4];
        #pragma unroll
        for (int mt = 0; mt < 4; ++mt) {
            uint32_t addr = sbA + (nb + mt * 16 + a_row) * 80 + (k0 + a_kh * 8) * 2;
            LDSM_X4(a[mt][0], a[mt][1], a[mt][2], a[mt][3], addr);
        }
        uint32_t bf[4][2];
        #pragma unroll
        for (int nt = 0; nt < 4; ++nt) {
            uint32_t addr = sbB + (rb + nt * 8 + b_row) * 80 + (k0 + b_ks * 8) * 2;
            LDSM_X2(bf[nt][0], bf[nt][1], addr);
        }
        #pragma unroll
        for (int mt = 0; mt < 4; ++mt)
            #pragma unroll
            for (int nt = 0; nt < 4; ++nt)
                MMA16816F(acc[mt][nt], a[mt][0], a[mt][1], a[mt][2], a[mt][3],
                          bf[nt][0], bf[nt][1]);
    }

    // ---- epilogue: frags -> smem D (conflict-free), then coalesced stream out
    __syncthreads();
    __half* D = (__half*)wsm;        // [128n][D_STR] 272B rows, 34816 B
    const int g   = lane >> 2;
    const int tig = lane & 3;
    #pragma unroll
    for (int nt = 0; nt < 4; ++nt) {
        const int rl = rb + nt * 8 + tig * 2;
        const int r  = rtile * 128 + rl;
        const float bv0 = __ldg(b2 + r);
        const float bv1 = __ldg(b2 + r + 1);
        #pragma unroll
        for (int mt = 0; mt < 4; ++mt) {
            const int n0 = nb + mt * 16 + g;
            *(__half2*)(D + n0 * D_STR + rl) =
                __floats2half2_rn(acc[mt][nt][0] + bv0, acc[mt][nt][1] + bv1);
            *(__half2*)(D + (n0 + 8) * D_STR + rl) =
                __floats2half2_rn(acc[mt][nt][2] + bv0, acc[mt][nt][3] + bv1);
        }
    }
    __syncthreads();

    // 2048 uint4: row = q>>4 (0..127), col = (q&15)*8 halfs -> 256B coalesced rows
    #pragma unroll
    for (int i = 0; i < 8; ++i) {
        int q = i * 256 + tid;
        int row = q >> 4, col = (q & 15) * 8;
        uint4 v = *(const uint4*)(D + row * D_STR + col);
        *(uint4*)(g_weight + (size_t)(ntile * 128 + row) * RTOT + rtile * 128 + col) = v;
    }
}

// ---------------------------------------------------------------------------
// Kernel 3: main GEMM via mma.sync fp16, single pass (proven).
// n REVERSED vs launch order so W reads hit L2 tiles wgen wrote last.
// ---------------------------------------------------------------------------
#define P_OFF   17408u
#define A_OFF   18432u
#define A_STR   176
#define SM_MAIN (18432 + 65 * 176)   // 29872 B

__global__ __launch_bounds__(128) void main_mma_kernel(
    const float* __restrict__ x, float* __restrict__ out)
{
    extern __shared__ __align__(1024) char smem[];
    const uint32_t sb = smem_u32(smem);
    const int tid  = threadIdx.x;
    const int wid  = tid >> 5;
    const int lane = tid & 31;
    const int n  = (N_ - 1) - blockIdx.x;     // reversed for L2 reuse of g_weight
    const int b  = n >> 10;
    const int t0 = (n & 1023) * 64;

    const float* xb = x + (size_t)b * CIN * T_ + t0;
    float* Xs = (float*)smem;
    float* P  = (float*)(smem + P_OFF);

    const uint4* wsrc = (const uint4*)(g_weight + (size_t)n * RTOT);
    uint4 wreg[8];
    #pragma unroll
    for (int i = 0; i < 8; ++i) wreg[i] = __ldg(wsrc + i * 128 + tid);

    #pragma unroll
    for (int i = 0; i < 8; ++i) {
        int f = i * 128 + tid;
        int ch = f >> 4, sc = (f & 15) * 4;
        float4 v = __ldg((const float4*)(xb + (size_t)ch * T_ + sc));
        *(float4*)(Xs + ch * 68 + sc) = v;
    }
    if (tid < 64) P[tid] = t0 ? __ldg(xb + (size_t)tid * T_ - 1) : 0.f;
    __syncthreads();

    if (tid < 16) {
        float4 p = *(const float4*)(P + tid * 4);
        sts64(sb + A_OFF + tid * 8,
              h2u(__floats2half2_rn(p.x, p.y)), h2u(__floats2half2_rn(p.z, p.w)));
    }
    #pragma unroll
    for (int i = 0; i < 8; ++i) {
        int idx = i * 128 + tid;
        int sp  = (idx & 63) + 1;
        int chg = idx >> 6;
        const float* xs = Xs + chg * 4 * 68 + (sp - 1);
        float e0 = xs[0], e1 = xs[68], e2 = xs[136], e3 = xs[204];
        sts64(sb + A_OFF + sp * A_STR + chg * 8,
              h2u(__floats2half2_rn(e0, e1)), h2u(__floats2half2_rn(e2, e3)));
    }
    __syncthreads();

    #pragma unroll
    for (int i = 0; i < 8; ++i) {
        int f4 = i * 128 + tid;
        int c = f4 >> 3, o0 = (f4 & 7) * 8;
        *(uint4*)(smem + c * 144 + o0 * 2) = wreg[i];
    }
    __syncthreads();

    const int s_base = (wid & 1) * 32;
    const int o_base = (wid >> 1) * 32;

    float acc[2][4][4];
    #pragma unroll
    for (int mt = 0; mt < 2; ++mt)
        #pragma unroll
        for (int nt = 0; nt < 4; ++nt)
            #pragma unroll
            for (int r = 0; r < 4; ++r) acc[mt][nt][r] = 0.f;

    const uint32_t a_row = lane & 15;
    const uint32_t a_kh  = lane >> 4;
    const uint32_t b_kr  = lane & 15;

    #pragma unroll
    for (int k = 0; k < 8; ++k) {
        const int rowoff = (k < 4) ? 1 : 0;
        const int chcol  = (k & 3) * 16;
        uint32_t a[2][4];
        #pragma unroll
        for (int mt = 0; mt < 2; ++mt) {
            uint32_t addr = sb + A_OFF
                          + (rowoff + s_base + mt * 16 + a_row) * A_STR
                          + (chcol + a_kh * 8) * 2;
            LDSM_X4(a[mt][0], a[mt][1], a[mt][2], a[mt][3], addr);
        }
        uint32_t bf[4][2];
        #pragma unroll
        for (int nt = 0; nt < 4; ++nt) {
            uint32_t addr = sb + (k * 16 + b_kr) * 144 + (o_base + nt * 8) * 2;
            LDSM_X2T(bf[nt][0], bf[nt][1], addr);
        }
        #pragma unroll
        for (int mt = 0; mt < 2; ++mt)
            #pragma unroll
            for (int nt = 0; nt < 4; ++nt)
                MMA16816F(acc[mt][nt], a[mt][0], a[mt][1], a[mt][2], a[mt][3],
                          bf[nt][0], bf[nt][1]);
    }

    const int g   = lane >> 2;
    const int tig = lane & 3;
    #pragma unroll
    for (int nt = 0; nt < 4; ++nt) {
        const int o = o_base + nt * 8 + 2 * tig;
        const float bv0 = __ldg(g_bias + (size_t)n * COUT + o);
        const float bv1 = __ldg(g_bias + (size_t)n * COUT + o + 1);
        #pragma unroll
        for (int mt = 0; mt < 2; ++mt) {
            const int s = s_base + mt * 16 + g;
            float* p0 = out + (size_t)(b * COUT + o) * T_ + t0 + s;
            float* p1 = p0 + T_;
            p0[0] = acc[mt][nt][0] + bv0;
            p1[0] = acc[mt][nt][1] + bv1;
            p0[8] = acc[mt][nt][2] + bv0;
            p1[8] = acc[mt][nt][3] + bv1;
        }
    }
}

// ---------------------------------------------------------------------------
extern "C" void kernel_launch(void* const* d_in, const int* in_sizes, int n_in,
                              void* d_out, int out_size)
{
    const float* x  = (const float*)d_in[0];
    const float* z  = (const float*)d_in[1];
    const float* w1 = (const float*)d_in[2];
    const float* b1 = (const float*)d_in[3];
    const float* w2 = (const float*)d_in[4];
    const float* b2 = (const float*)d_in[5];
    const float* w3 = (const float*)d_in[6];
    const float* b3 = (const float*)d_in[7];
    const float* w4 = (const float*)d_in[8];
    const float* b4 = (const float*)d_in[9];
    float* out = (float*)d_out;

    cudaFuncSetAttribute(hyper_kernel,    cudaFuncAttributeMaxDynamicSharedMemorySize, 62720);
    cudaFuncSetAttribute(main_mma_kernel, cudaFuncAttributeMaxDynamicSharedMemorySize, SM_MAIN);

    hyper_kernel<<<dim3(32, 8), 256, 62720>>>(z, w1, b1, w3, b3, w4, b4);
    wgen_kernel<<<dim3(64, 64), 256>>>(w2, b2);
    main_mma_kernel<<<N_, 128, SM_MAIN>>>(x, out);
}

// round 12
// speedup vs baseline: 5.2957x; 1.1315x over previous
#include <cuda_runtime.h>
#include <cuda_fp16.h>
#include <cstdint>

// Problem constants
#define B_   8
#define K_   1024
#define N_   (B_ * K_)
#define S_   64
#define T_   65536
#define CIN  64
#define COUT 64
#define CKS  128
#define HID_ 32
#define ZDIM 128
#define RTOT (CKS * COUT)

// Device scratch
__device__ __half g_h1h[N_ * HID_];              // fp16 [n][j]
__device__ float  g_bias[N_ * COUT];
__device__ __half g_weight[(size_t)N_ * RTOT];   // fp16 [n][r], r = c*64+o

// ---------------------------------------------------------------------------
// PTX helpers
// ---------------------------------------------------------------------------
__device__ __forceinline__ uint32_t smem_u32(const void* p) {
    uint32_t a;
    asm("{ .reg .u64 t; cvta.to.shared.u64 t, %1; cvt.u32.u64 %0, t; }" : "=r"(a) : "l"(p));
    return a;
}
#define LDSM_X4(r0,r1,r2,r3,addr) \
    asm volatile("ldmatrix.sync.aligned.m8n8.x4.shared.b16 {%0,%1,%2,%3}, [%4];" \
        : "=r"(r0),"=r"(r1),"=r"(r2),"=r"(r3) : "r"(addr))
#define LDSM_X2(r0,r1,addr) \
    asm volatile("ldmatrix.sync.aligned.m8n8.x2.shared.b16 {%0,%1}, [%2];" \
        : "=r"(r0),"=r"(r1) : "r"(addr))
#define LDSM_X2T(r0,r1,addr) \
    asm volatile("ldmatrix.sync.aligned.m8n8.x2.trans.shared.b16 {%0,%1}, [%2];" \
        : "=r"(r0),"=r"(r1) : "r"(addr))
#define MMA16816F(d,a0,a1,a2,a3,b0,b1) \
    asm volatile("mma.sync.aligned.m16n8k16.row.col.f32.f16.f16.f32 " \
        "{%0,%1,%2,%3}, {%4,%5,%6,%7}, {%8,%9}, {%0,%1,%2,%3};" \
        : "+f"((d)[0]),"+f"((d)[1]),"+f"((d)[2]),"+f"((d)[3]) \
        : "r"(a0),"r"(a1),"r"(a2),"r"(a3),"r"(b0),"r"(b1))

#define CPA16(saddr, gptr) \
    asm volatile("cp.async.cg.shared.global [%0], [%1], 16;" \
        :: "r"(saddr), "l"(gptr) : "memory")
#define CPA_COMMIT() asm volatile("cp.async.commit_group;" ::: "memory")
#define CPA_WAIT0()  asm volatile("cp.async.wait_group 0;" ::: "memory")

__device__ __forceinline__ void sts64(uint32_t addr, uint32_t a, uint32_t b) {
    asm volatile("st.shared.v2.b32 [%0], {%1,%2};" :: "r"(addr), "r"(a), "r"(b));
}
__device__ __forceinline__ uint32_t h2u(__half2 h) {
    return *reinterpret_cast<uint32_t*>(&h);
}

// ---------------------------------------------------------------------------
// Kernel 1: hyper MLP heads — register-blocked (proven, 12us)
// ---------------------------------------------------------------------------
__global__ __launch_bounds__(256) void hyper_kernel(
    const float* __restrict__ z,
    const float* __restrict__ w1, const float* __restrict__ b1,
    const float* __restrict__ w3, const float* __restrict__ b3,
    const float* __restrict__ w4, const float* __restrict__ b4)
{
    extern __shared__ float hs[];
    float* zs   = hs;
    float* w1sT = hs + 4096;
    float* w3sT = hs + 8320;
    float* w4sT = hs + 12544;
    float* h3s  = hs + 14624;

    const int b  = blockIdx.y;
    const int k0 = blockIdx.x * 32;
    const int tid = threadIdx.x;

    #pragma unroll
    for (int i = 0; i < 16; ++i) {
        int f = i * 256 + tid;
        zs[f] = z[((size_t)(b * ZDIM + (f >> 5))) * K_ + k0 + (f & 31)];
    }
    #pragma unroll
    for (int i = 0; i < 16; ++i) {
        int f = i * 256 + tid;
        w1sT[(f & 127) * 33 + (f >> 7)] = w1[f];
    }
    #pragma unroll
    for (int i = 0; i < 16; ++i) {
        int f = i * 256 + tid;
        w3sT[(f & 127) * 33 + (f >> 7)] = w3[f];
    }
    #pragma unroll
    for (int i = 0; i < 8; ++i) {
        int f = i * 256 + tid;
        w4sT[(f & 31) * 65 + (f >> 5)] = w4[f];
    }
    __syncthreads();

    {
        const int jo  = tid & 31;
        const int kkg = tid >> 5;
        float a1[4] = {b1[jo], b1[jo], b1[jo], b1[jo]};
        float a3[4] = {b3[jo], b3[jo], b3[jo], b3[jo]};
        #pragma unroll 8
        for (int j = 0; j < ZDIM; ++j) {
            float4 zv = *(const float4*)(zs + j * 32 + kkg * 4);
            float wa = w1sT[j * 33 + jo];
            float wb = w3sT[j * 33 + jo];
            a1[0] += wa * zv.x; a1[1] += wa * zv.y; a1[2] += wa * zv.z; a1[3] += wa * zv.w;
            a3[0] += wb * zv.x; a3[1] += wb * zv.y; a3[2] += wb * zv.z; a3[3] += wb * zv.w;
        }
        #pragma unroll
        for (int u = 0; u < 4; ++u) {
            int kk = kkg * 4 + u;
            g_h1h[(size_t)(b * K_ + k0 + kk) * HID_ + jo] =
                __float2half(fmaxf(a1[u], 0.f));
            h3s[kk * 33 + jo] = fmaxf(a3[u], 0.f);
        }
    }
    __syncthreads();

    {
        const int o  = tid & 63;
        const int kg = tid >> 6;
        float ab[8];
        float bv = b4[o];
        #pragma unroll
        for (int u = 0; u < 8; ++u) ab[u] = bv;
        #pragma unroll
        for (int j = 0; j < HID_; ++j) {
            float w = w4sT[j * 65 + o];
            #pragma unroll
            for (int u = 0; u < 8; ++u)
                ab[u] += w * h3s[(kg * 8 + u) * 33 + j];
        }
        #pragma unroll
        for (int u = 0; u < 8; ++u)
            g_bias[(size_t)(b * K_ + k0 + kg * 8 + u) * COUT + o] = ab[u];
    }
}

// ---------------------------------------------------------------------------
// Kernel 2: weight-gen via mma.sync fp16 (proven R10)
// ---------------------------------------------------------------------------
#define D_STR 136

__global__ __launch_bounds__(256) void wgen_kernel(
    const float* __restrict__ w2, const float* __restrict__ b2)
{
    __shared__ __align__(16) char wsm[128 * D_STR * 2];
    __half* Ah = (__half*)wsm;
    __half* Bh = (__half*)(wsm + 10240);

    const int rtile = blockIdx.x;
    const int ntile = blockIdx.y;
    const int tid  = threadIdx.x;
    const int wid  = tid >> 5;
    const int lane = tid & 31;

    const uint4* hsrc = (const uint4*)(g_h1h + (size_t)ntile * 128 * HID_);
    #pragma unroll
    for (int i = 0; i < 2; ++i) {
        int q = i * 256 + tid;
        int n = q >> 2, jq = q & 3;
        *(uint4*)&Ah[n * 40 + jq * 8] = __ldg(hsrc + q);
    }
    const float4* wsrc = (const float4*)(w2 + (size_t)rtile * 128 * HID_);
    #pragma unroll
    for (int i = 0; i < 4; ++i) {
        int q = i * 256 + tid;
        int r = q >> 3, jq = q & 7;
        float4 v = __ldg(wsrc + q);
        uint32_t p0 = h2u(__floats2half2_rn(v.x, v.y));
        uint32_t p1 = h2u(__floats2half2_rn(v.z, v.w));
        sts64(smem_u32(&Bh[r * 40 + jq * 4]), p0, p1);
    }
    __syncthreads();

    const uint32_t sbA = smem_u32(Ah);
    const uint32_t sbB = smem_u32(Bh);
    const int nb = (wid & 1) * 64;
    const int rb = (wid >> 1) * 32;

    float acc[4][4][4];
    #pragma unroll
    for (int mt = 0; mt < 4; ++mt)
        #pragma unroll
        for (int nt = 0; nt < 4; ++nt)
            #pragma unroll
            for (int u = 0; u < 4; ++u) acc[mt][nt][u] = 0.f;

    const int a_row = lane & 15;
    const int a_kh  = lane >> 4;
    const int b_row = lane & 7;
    const int b_ks  = (lane >> 3) & 1;

    #pragma unroll
    for (int ks = 0; ks < 2; ++ks) {
        const int k0 = ks * 16;
        uint32_t a[4][4];
        #pragma unroll
        for (int mt = 0; mt < 4; ++mt) {
            uint32_t addr = sbA + (nb + mt * 16 + a_row) * 80 + (k0 + a_kh * 8) * 2;
            LDSM_X4(a[mt][0], a[mt][1], a[mt][2], a[mt][3], addr);
        }
        uint32_t bf[4][2];
        #pragma unroll
        for (int nt = 0; nt < 4; ++nt) {
            uint32_t addr = sbB + (rb + nt * 8 + b_row) * 80 + (k0 + b_ks * 8) * 2;
            LDSM_X2(bf[nt][0], bf[nt][1], addr);
        }
        #pragma unroll
        for (int mt = 0; mt < 4; ++mt)
            #pragma unroll
            for (int nt = 0; nt < 4; ++nt)
                MMA16816F(acc[mt][nt], a[mt][0], a[mt][1], a[mt][2], a[mt][3],
                          bf[nt][0], bf[nt][1]);
    }

    __syncthreads();
    __half* D = (__half*)wsm;
    const int g   = lane >> 2;
    const int tig = lane & 3;
    #pragma unroll
    for (int nt = 0; nt < 4; ++nt) {
        const int rl = rb + nt * 8 + tig * 2;
        const int r  = rtile * 128 + rl;
        const float bv0 = __ldg(b2 + r);
        const float bv1 = __ldg(b2 + r + 1);
        #pragma unroll
        for (int mt = 0; mt < 4; ++mt) {
            const int n0 = nb + mt * 16 + g;
            *(__half2*)(D + n0 * D_STR + rl) =
                __floats2half2_rn(acc[mt][nt][0] + bv0, acc[mt][nt][1] + bv1);
            *(__half2*)(D + (n0 + 8) * D_STR + rl) =
                __floats2half2_rn(acc[mt][nt][2] + bv0, acc[mt][nt][3] + bv1);
        }
    }
    __syncthreads();

    #pragma unroll
    for (int i = 0; i < 8; ++i) {
        int q = i * 256 + tid;
        int row = q >> 4, col = (q & 15) * 8;
        uint4 v = *(const uint4*)(D + row * D_STR + col);
        *(uint4*)(g_weight + (size_t)(ntile * 128 + row) * RTOT + rtile * 128 + col) = v;
    }
}

// ---------------------------------------------------------------------------
// Kernel 3: main GEMM via mma.sync fp16, cp.async phases + staged epilogue.
// Region0 [0,18432): x fp32 staging(17408)+P(1024) -> B fp16 [c][o] 144B rows
//                    -> out fp32 staging [o][s] 288B rows.
// Region1 [18432, 29872): A fp16 [sp][ch] 176B rows.
// ---------------------------------------------------------------------------
#define P_OFF   17408u
#define A_OFF   18432u
#define A_STR   176
#define O_STRF  72          // floats per out-stage row (288 B)
#define SM_MAIN (18432 + 65 * 176)   // 29872 B

__global__ __launch_bounds__(128, 6) void main_mma_kernel(
    const float* __restrict__ x, float* __restrict__ out)
{
    extern __shared__ __align__(1024) char smem[];
    const uint32_t sb = smem_u32(smem);
    const int tid  = threadIdx.x;
    const int wid  = tid >> 5;
    const int lane = tid & 31;
    const int n  = (N_ - 1) - blockIdx.x;
    const int b  = n >> 10;
    const int t0 = (n & 1023) * 64;

    const float* xb = x + (size_t)b * CIN * T_ + t0;
    float* Xs = (float*)smem;                 // [ch][s], stride 68 floats
    float* P  = (float*)(smem + P_OFF);

    // phase 0: x -> staging via cp.async (no register roundtrip)
    #pragma unroll
    for (int i = 0; i < 8; ++i) {
        int f = i * 128 + tid;
        int ch = f >> 4, sc = (f & 15) * 4;
        CPA16(sb + (uint32_t)(ch * 68 + sc) * 4, xb + (size_t)ch * T_ + sc);
    }
    if (tid < 64) P[tid] = t0 ? __ldg(xb + (size_t)tid * T_ - 1) : 0.f;
    CPA_COMMIT();
    CPA_WAIT0();
    __syncthreads();

    // phase 1: A-build (fp16 [sp][ch], rows 0..64)
    if (tid < 16) {
        float4 p = *(const float4*)(P + tid * 4);
        sts64(sb + A_OFF + tid * 8,
              h2u(__floats2half2_rn(p.x, p.y)), h2u(__floats2half2_rn(p.z, p.w)));
    }
    #pragma unroll
    for (int i = 0; i < 8; ++i) {
        int idx = i * 128 + tid;
        int sp  = (idx & 63) + 1;
        int chg = idx >> 6;
        const float* xs = Xs + chg * 4 * 68 + (sp - 1);
        float e0 = xs[0], e1 = xs[68], e2 = xs[136], e3 = xs[204];
        sts64(sb + A_OFF + sp * A_STR + chg * 8,
              h2u(__floats2half2_rn(e0, e1)), h2u(__floats2half2_rn(e2, e3)));
    }
    __syncthreads();   // staging fully consumed -> region0 reusable as B

    // phase 2: W -> B (region0) via cp.async, [c][o] rows 144B
    {
        const uint4* wsrc = (const uint4*)(g_weight + (size_t)n * RTOT);
        #pragma unroll
        for (int i = 0; i < 8; ++i) {
            int f4 = i * 128 + tid;
            int c = f4 >> 3, o0 = (f4 & 7) * 8;
            CPA16(sb + (uint32_t)(c * 144 + o0 * 2), wsrc + f4);
        }
        CPA_COMMIT();
        CPA_WAIT0();
    }
    __syncthreads();

    // phase 3: MMA mainloop
    const int s_base = (wid & 1) * 32;
    const int o_base = (wid >> 1) * 32;

    float acc[2][4][4];
    #pragma unroll
    for (int mt = 0; mt < 2; ++mt)
        #pragma unroll
        for (int nt = 0; nt < 4; ++nt)
            #pragma unroll
            for (int r = 0; r < 4; ++r) acc[mt][nt][r] = 0.f;

    const uint32_t a_row = lane & 15;
    const uint32_t a_kh  = lane >> 4;
    const uint32_t b_kr  = lane & 15;

    #pragma unroll
    for (int k = 0; k < 8; ++k) {
        const int rowoff = (k < 4) ? 1 : 0;
        const int chcol  = (k & 3) * 16;
        uint32_t a[2][4];
        #pragma unroll
        for (int mt = 0; mt < 2; ++mt) {
            uint32_t addr = sb + A_OFF
                          + (rowoff + s_base + mt * 16 + a_row) * A_STR
                          + (chcol + a_kh * 8) * 2;
            LDSM_X4(a[mt][0], a[mt][1], a[mt][2], a[mt][3], addr);
        }
        uint32_t bf[4][2];
        #pragma unroll
        for (int nt = 0; nt < 4; ++nt) {
            uint32_t addr = sb + (k * 16 + b_kr) * 144 + (o_base + nt * 8) * 2;
            LDSM_X2T(bf[nt][0], bf[nt][1], addr);
        }
        #pragma unroll
        for (int mt = 0; mt < 2; ++mt)
            #pragma unroll
            for (int nt = 0; nt < 4; ++nt)
                MMA16816F(acc[mt][nt], a[mt][0], a[mt][1], a[mt][2], a[mt][3],
                          bf[nt][0], bf[nt][1]);
    }
    __syncthreads();   // all LDSM done -> region0 reusable as out staging

    // phase 4: epilogue — frags + bias -> smem [o][s] (288B rows), then
    // fully-coalesced float4 stores to gmem.
    {
        float* D = (float*)smem;             // [64 o][O_STRF]
        const int g   = lane >> 2;
        const int tig = lane & 3;
        #pragma unroll
        for (int nt = 0; nt < 4; ++nt) {
            const int o = o_base + nt * 8 + 2 * tig;
            const float bv0 = __ldg(g_bias + (size_t)n * COUT + o);
            const float bv1 = __ldg(g_bias + (size_t)n * COUT + o + 1);
            #pragma unroll
            for (int mt = 0; mt < 2; ++mt) {
                const int s = s_base + mt * 16 + g;
                D[o * O_STRF + s]           = acc[mt][nt][0] + bv0;
                D[(o + 1) * O_STRF + s]     = acc[mt][nt][1] + bv1;
                D[o * O_STRF + s + 8]       = acc[mt][nt][2] + bv0;
                D[(o + 1) * O_STRF + s + 8] = acc[mt][nt][3] + bv1;
            }
        }
        __syncthreads();

        // 1024 float4 = 64 rows x 16; 8 per thread, 256B coalesced per row
        float* ob = out + (size_t)b * COUT * T_ + t0;
        #pragma unroll
        for (int i = 0; i < 8; ++i) {
            int q = i * 128 + tid;
            int row = q >> 4, col = (q & 15) * 4;
            float4 v = *(const float4*)(D + row * O_STRF + col);
            *(float4*)(ob + (size_t)row * T_ + col) = v;
        }
    }
}

// ---------------------------------------------------------------------------
extern "C" void kernel_launch(void* const* d_in, const int* in_sizes, int n_in,
                              void* d_out, int out_size)
{
    const float* x  = (const float*)d_in[0];
    const float* z  = (const float*)d_in[1];
    const float* w1 = (const float*)d_in[2];
    const float* b1 = (const float*)d_in[3];
    const float* w2 = (const float*)d_in[4];
    const float* b2 = (const float*)d_in[5];
    const float* w3 = (const float*)d_in[6];
    const float* b3 = (const float*)d_in[7];
    const float* w4 = (const float*)d_in[8];
    const float* b4 = (const float*)d_in[9];
    float* out = (float*)d_out;

    cudaFuncSetAttribute(hyper_kernel,    cudaFuncAttributeMaxDynamicSharedMemorySize, 62720);
    cudaFuncSetAttribute(main_mma_kernel, cudaFuncAttributeMaxDynamicSharedMemorySize, SM_MAIN);

    hyper_kernel<<<dim3(32, 8), 256, 62720>>>(z, w1, b1, w3, b3, w4, b4);
    wgen_kernel<<<dim3(64, 64), 256>>>(w2, b2);
    main_mma_kernel<<<N_, 128, SM_MAIN>>>(x, out);
}